// round 5
// baseline (speedup 1.0000x reference)
#include <cuda_runtime.h>
#include <math.h>

#define B_   2
#define T_   2048
#define S_   2048
#define E_   1024
#define H_   16
#define DH_  64
#define SCALE_ 0.125f
#define CLAMP_V 50000.0f
#define NBLK 16              // S_/128 score col-blocks per row

// Scratch (device globals: no allocations allowed)
__device__ float  g_Qp[B_ * T_ * E_];
__device__ float  g_Kp[B_ * S_ * E_];
__device__ float  g_Vp[B_ * S_ * E_];
__device__ float  g_ctx[B_ * T_ * E_];
__device__ float2 g_part[(size_t)B_ * H_ * T_ * NBLK];

// ---------------------------------------------------------------------------
__device__ __forceinline__ unsigned cvt_tf32(float x) {
    unsigned r;
    asm("cvt.rna.tf32.f32 %0, %1;" : "=r"(r) : "f"(x));
    return r;
}

__device__ __forceinline__ void mma8(float* d, const unsigned* a, const unsigned* b) {
    asm volatile(
        "mma.sync.aligned.m16n8k8.row.col.f32.tf32.tf32.f32 "
        "{%0,%1,%2,%3}, {%4,%5,%6,%7}, {%8,%9}, {%0,%1,%2,%3};"
        : "+f"(d[0]), "+f"(d[1]), "+f"(d[2]), "+f"(d[3])
        : "r"(a[0]), "r"(a[1]), "r"(a[2]), "r"(a[3]), "r"(b[0]), "r"(b[1]));
}

__device__ __forceinline__ void softmax_merge(float& m, float& s, float om, float os) {
    float nm = fmaxf(m, om);
    if (nm == -INFINITY) { m = nm; s = 0.f; return; }
    s = s * __expf(m - nm) + os * __expf(om - nm);
    m = nm;
}

// ---------------------------------------------------------------------------
// NT GEMM + bias + alpha, tf32 mma.sync.  BM=BN=128, BK=16, 512 threads,
// 16 warps in a 4x4 grid, warp tile 32x32.  Loader: row=tid&127 (bank-free).
// ---------------------------------------------------------------------------
__global__ __launch_bounds__(512) void gemm_nt_bias(
    const float* __restrict__ A, const float* __restrict__ Bm,
    const float* __restrict__ bias, float* __restrict__ C,
    int K, int lda, int ldb, int ldc, float alpha)
{
    __shared__ float As[2][16][136];
    __shared__ float Bs[2][16][136];
    const int tid = threadIdx.x;
    const int lane = tid & 31, w = tid >> 5;
    const int wm = w & 3, wn = w >> 2;
    const int lr = lane >> 2, lc = lane & 3;
    const int bm = blockIdx.y * 128, bn = blockIdx.x * 128;
    const int lrow = tid & 127, lk = (tid >> 7) * 4;

    const float* Ap = A + (size_t)(bm + lrow) * lda + lk;
    const float* Bp = Bm + (size_t)(bn + lrow) * ldb + lk;

    float acc[2][4][4] = {};

    {
        float4 a = *(const float4*)(Ap);
        float4 b = *(const float4*)(Bp);
        As[0][lk + 0][lrow] = __uint_as_float(cvt_tf32(a.x));
        As[0][lk + 1][lrow] = __uint_as_float(cvt_tf32(a.y));
        As[0][lk + 2][lrow] = __uint_as_float(cvt_tf32(a.z));
        As[0][lk + 3][lrow] = __uint_as_float(cvt_tf32(a.w));
        Bs[0][lk + 0][lrow] = __uint_as_float(cvt_tf32(b.x));
        Bs[0][lk + 1][lrow] = __uint_as_float(cvt_tf32(b.y));
        Bs[0][lk + 2][lrow] = __uint_as_float(cvt_tf32(b.z));
        Bs[0][lk + 3][lrow] = __uint_as_float(cvt_tf32(b.w));
    }
    __syncthreads();

    const int NC = K >> 4;
    int buf = 0;
    for (int kc = 0; kc < NC; kc++) {
        const bool more = (kc + 1) < NC;
        float4 na, nb;
        if (more) {
            na = *(const float4*)(Ap + (kc + 1) * 16);
            nb = *(const float4*)(Bp + (kc + 1) * 16);
        }
#pragma unroll
        for (int kt = 0; kt < 2; kt++) {
            const int kk = kt * 8;
            unsigned af[2][4], bf[4][2];
#pragma unroll
            for (int i = 0; i < 2; i++) {
                int mb = wm * 32 + i * 16 + lr;
                af[i][0] = __float_as_uint(As[buf][kk + lc][mb]);
                af[i][1] = __float_as_uint(As[buf][kk + lc][mb + 8]);
                af[i][2] = __float_as_uint(As[buf][kk + 4 + lc][mb]);
                af[i][3] = __float_as_uint(As[buf][kk + 4 + lc][mb + 8]);
            }
#pragma unroll
            for (int j = 0; j < 4; j++) {
                int nbx = wn * 32 + j * 8 + lr;
                bf[j][0] = __float_as_uint(Bs[buf][kk + lc][nbx]);
                bf[j][1] = __float_as_uint(Bs[buf][kk + 4 + lc][nbx]);
            }
#pragma unroll
            for (int i = 0; i < 2; i++)
#pragma unroll
                for (int j = 0; j < 4; j++)
                    mma8(acc[i][j], af[i], bf[j]);
        }
        if (more) {
            buf ^= 1;
            As[buf][lk + 0][lrow] = __uint_as_float(cvt_tf32(na.x));
            As[buf][lk + 1][lrow] = __uint_as_float(cvt_tf32(na.y));
            As[buf][lk + 2][lrow] = __uint_as_float(cvt_tf32(na.z));
            As[buf][lk + 3][lrow] = __uint_as_float(cvt_tf32(na.w));
            Bs[buf][lk + 0][lrow] = __uint_as_float(cvt_tf32(nb.x));
            Bs[buf][lk + 1][lrow] = __uint_as_float(cvt_tf32(nb.y));
            Bs[buf][lk + 2][lrow] = __uint_as_float(cvt_tf32(nb.z));
            Bs[buf][lk + 3][lrow] = __uint_as_float(cvt_tf32(nb.w));
            __syncthreads();
        }
    }

#pragma unroll
    for (int j = 0; j < 4; j++) {
        int col = bn + wn * 32 + j * 8 + lc * 2;
        float b0v = bias[col], b1v = bias[col + 1];
#pragma unroll
        for (int i = 0; i < 2; i++) {
            int row = bm + wm * 32 + i * 16 + lr;
            *(float2*)(C + (size_t)row * ldc + col) =
                make_float2(alpha * (acc[i][j][0] + b0v), alpha * (acc[i][j][1] + b1v));
            *(float2*)(C + (size_t)(row + 8) * ldc + col) =
                make_float2(alpha * (acc[i][j][2] + b0v), alpha * (acc[i][j][3] + b1v));
        }
    }
}

// ---------------------------------------------------------------------------
// Scores: per (b,h) 128x128 tile of clamp(Q.K^T) + mask -> -inf, raw store,
// per-(row, colblock) softmax partials.  K=64 (4 chunks of 16).  512 threads.
// ---------------------------------------------------------------------------
__global__ __launch_bounds__(512) void attn_scores(
    const float* __restrict__ Qp, const float* __restrict__ Kp,
    const int* __restrict__ mask, float* __restrict__ P,
    float2* __restrict__ part)
{
    __shared__ float As[2][16][136];
    __shared__ float Bs[2][16][136];
    __shared__ float2 red[4][128];
    __shared__ int msk[128];

    const int bh = blockIdx.z, b = bh >> 4, h = bh & 15;
    const float* A  = Qp + (size_t)b * T_ * E_ + h * DH_;
    const float* Bm = Kp + (size_t)b * S_ * E_ + h * DH_;
    float* C = P + (size_t)bh * T_ * S_;

    const int tid = threadIdx.x;
    const int lane = tid & 31, w = tid >> 5;
    const int wm = w & 3, wn = w >> 2;
    const int lr = lane >> 2, lc = lane & 3;
    const int bm = blockIdx.y * 128, bn = blockIdx.x * 128;
    const int lrow = tid & 127, lk = (tid >> 7) * 4;

    const float* Ap = A + (size_t)(bm + lrow) * E_ + lk;
    const float* Bp = Bm + (size_t)(bn + lrow) * E_ + lk;

    float acc[2][4][4] = {};

    if (tid < 128) msk[tid] = mask[(size_t)b * S_ + bn + tid];
    {
        float4 a = *(const float4*)(Ap);
        float4 bb = *(const float4*)(Bp);
        As[0][lk + 0][lrow] = __uint_as_float(cvt_tf32(a.x));
        As[0][lk + 1][lrow] = __uint_as_float(cvt_tf32(a.y));
        As[0][lk + 2][lrow] = __uint_as_float(cvt_tf32(a.z));
        As[0][lk + 3][lrow] = __uint_as_float(cvt_tf32(a.w));
        Bs[0][lk + 0][lrow] = __uint_as_float(cvt_tf32(bb.x));
        Bs[0][lk + 1][lrow] = __uint_as_float(cvt_tf32(bb.y));
        Bs[0][lk + 2][lrow] = __uint_as_float(cvt_tf32(bb.z));
        Bs[0][lk + 3][lrow] = __uint_as_float(cvt_tf32(bb.w));
    }
    __syncthreads();

    int buf = 0;
#pragma unroll
    for (int kc = 0; kc < 4; kc++) {
        const bool more = kc < 3;
        float4 na, nb;
        if (more) {
            na = *(const float4*)(Ap + (kc + 1) * 16);
            nb = *(const float4*)(Bp + (kc + 1) * 16);
        }
#pragma unroll
        for (int kt = 0; kt < 2; kt++) {
            const int kk = kt * 8;
            unsigned af[2][4], bf[4][2];
#pragma unroll
            for (int i = 0; i < 2; i++) {
                int mb = wm * 32 + i * 16 + lr;
                af[i][0] = __float_as_uint(As[buf][kk + lc][mb]);
                af[i][1] = __float_as_uint(As[buf][kk + lc][mb + 8]);
                af[i][2] = __float_as_uint(As[buf][kk + 4 + lc][mb]);
                af[i][3] = __float_as_uint(As[buf][kk + 4 + lc][mb + 8]);
            }
#pragma unroll
            for (int j = 0; j < 4; j++) {
                int nbx = wn * 32 + j * 8 + lr;
                bf[j][0] = __float_as_uint(Bs[buf][kk + lc][nbx]);
                bf[j][1] = __float_as_uint(Bs[buf][kk + 4 + lc][nbx]);
            }
#pragma unroll
            for (int i = 0; i < 2; i++)
#pragma unroll
                for (int j = 0; j < 4; j++)
                    mma8(acc[i][j], af[i], bf[j]);
        }
        if (more) {
            buf ^= 1;
            As[buf][lk + 0][lrow] = __uint_as_float(cvt_tf32(na.x));
            As[buf][lk + 1][lrow] = __uint_as_float(cvt_tf32(na.y));
            As[buf][lk + 2][lrow] = __uint_as_float(cvt_tf32(na.z));
            As[buf][lk + 3][lrow] = __uint_as_float(cvt_tf32(na.w));
            Bs[buf][lk + 0][lrow] = __uint_as_float(cvt_tf32(nb.x));
            Bs[buf][lk + 1][lrow] = __uint_as_float(cvt_tf32(nb.y));
            Bs[buf][lk + 2][lrow] = __uint_as_float(cvt_tf32(nb.z));
            Bs[buf][lk + 3][lrow] = __uint_as_float(cvt_tf32(nb.w));
            __syncthreads();
        }
    }

    // epilogue: clamp + mask + raw store + per-row (m,s)
#pragma unroll
    for (int i = 0; i < 2; i++) {
        int rl = wm * 32 + i * 16 + lr;
        float vlo[8], vhi[8];
        float m_lo = -INFINITY, m_hi = -INFINITY;
#pragma unroll
        for (int j = 0; j < 4; j++) {
            int lcol = wn * 32 + j * 8 + lc * 2;
            bool k0 = msk[lcol] != 0, k1 = msk[lcol + 1] != 0;
            float a0 = fminf(fmaxf(acc[i][j][0], -CLAMP_V), CLAMP_V);
            float a1 = fminf(fmaxf(acc[i][j][1], -CLAMP_V), CLAMP_V);
            float a2 = fminf(fmaxf(acc[i][j][2], -CLAMP_V), CLAMP_V);
            float a3 = fminf(fmaxf(acc[i][j][3], -CLAMP_V), CLAMP_V);
            vlo[j * 2]     = k0 ? a0 : -INFINITY;
            vlo[j * 2 + 1] = k1 ? a1 : -INFINITY;
            vhi[j * 2]     = k0 ? a2 : -INFINITY;
            vhi[j * 2 + 1] = k1 ? a3 : -INFINITY;
            m_lo = fmaxf(m_lo, fmaxf(vlo[j * 2], vlo[j * 2 + 1]));
            m_hi = fmaxf(m_hi, fmaxf(vhi[j * 2], vhi[j * 2 + 1]));
            int col = bn + lcol;
            *(float2*)(C + (size_t)(bm + rl) * S_ + col)     = make_float2(vlo[j * 2], vlo[j * 2 + 1]);
            *(float2*)(C + (size_t)(bm + rl + 8) * S_ + col) = make_float2(vhi[j * 2], vhi[j * 2 + 1]);
        }
        float s_lo = 0.f, s_hi = 0.f;
        if (m_lo != -INFINITY) {
#pragma unroll
            for (int u = 0; u < 8; u++) s_lo += __expf(vlo[u] - m_lo);
        }
        if (m_hi != -INFINITY) {
#pragma unroll
            for (int u = 0; u < 8; u++) s_hi += __expf(vhi[u] - m_hi);
        }
#pragma unroll
        for (int off = 1; off <= 2; off <<= 1) {
            softmax_merge(m_lo, s_lo, __shfl_xor_sync(0xffffffffu, m_lo, off),
                                      __shfl_xor_sync(0xffffffffu, s_lo, off));
            softmax_merge(m_hi, s_hi, __shfl_xor_sync(0xffffffffu, m_hi, off),
                                      __shfl_xor_sync(0xffffffffu, s_hi, off));
        }
        if (lc == 0) {
            red[wn][rl]     = make_float2(m_lo, s_lo);
            red[wn][rl + 8] = make_float2(m_hi, s_hi);
        }
    }
    __syncthreads();
    if (tid < 128) {
        float m = -INFINITY, s = 0.f;
#pragma unroll
        for (int j = 0; j < 4; j++) {
            float2 p = red[j][tid];
            softmax_merge(m, s, p.x, p.y);
        }
        part[((size_t)bh * T_ + bm + tid) * NBLK + blockIdx.x] = make_float2(m, s);
    }
}

// ---------------------------------------------------------------------------
// PV: merges per-row stats from partials, reads raw scores, p=exp(v-m)*inv,
// writes normalized P back, Ctx = P @ V.  BM=128, BN=64, BK=16, 256 threads,
// 8 warps in 4x2 grid, warp tile 32x32.
// ---------------------------------------------------------------------------
__global__ __launch_bounds__(256) void attn_pv(
    float* __restrict__ P, const float* __restrict__ Vp,
    const float2* __restrict__ part, float* __restrict__ Ctx)
{
    __shared__ float As[2][16][136];
    __shared__ float Bs[2][16][68];
    __shared__ float2 sh_st[128];

    const int bh = blockIdx.y, b = bh >> 4, h = bh & 15;
    float* A = P + (size_t)bh * T_ * S_;
    const float* Bm = Vp + (size_t)b * S_ * E_ + h * DH_;
    float* C = Ctx + (size_t)b * T_ * E_ + h * DH_;

    const int tid = threadIdx.x;
    const int lane = tid & 31, w = tid >> 5;
    const int wm = w & 3, wn = w >> 2;
    const int lr = lane >> 2, lc = lane & 3;
    const int bm = blockIdx.x * 128;

    // merge row stats
    if (tid < 128) {
        float m = -INFINITY, s = 0.f;
#pragma unroll
        for (int j = 0; j < NBLK; j++) {
            float2 p = part[((size_t)bh * T_ + bm + tid) * NBLK + j];
            softmax_merge(m, s, p.x, p.y);
        }
        sh_st[tid] = make_float2(m, 1.f / s);
    }
    __syncthreads();

    const int arow = tid & 127, ah = tid >> 7;      // ah in {0,1}: k-halves
    const int ak = ah * 8;
    float* Pr = A + (size_t)(bm + arow) * S_ + ak;
    const float mrow = sh_st[arow].x, inv = sh_st[arow].y;

    const int sidx = tid >> 4, d4 = (tid & 15) * 4; // B loader: 16 s-rows x 64 d
    const float* Vb = Bm;

    float acc[2][4][4] = {};

    // prologue: stage chunk 0
    {
#pragma unroll
        for (int u2 = 0; u2 < 2; u2++) {
            float4 v = *(float4*)(Pr + u2 * 4);
            v.x = __expf(v.x - mrow) * inv;
            v.y = __expf(v.y - mrow) * inv;
            v.z = __expf(v.z - mrow) * inv;
            v.w = __expf(v.w - mrow) * inv;
            *(float4*)(Pr + u2 * 4) = v;
            As[0][ak + u2 * 4 + 0][arow] = __uint_as_float(cvt_tf32(v.x));
            As[0][ak + u2 * 4 + 1][arow] = __uint_as_float(cvt_tf32(v.y));
            As[0][ak + u2 * 4 + 2][arow] = __uint_as_float(cvt_tf32(v.z));
            As[0][ak + u2 * 4 + 3][arow] = __uint_as_float(cvt_tf32(v.w));
        }
        float4 bv = *(const float4*)(Vb + (size_t)sidx * E_ + d4);
        Bs[0][sidx][d4 + 0] = __uint_as_float(cvt_tf32(bv.x));
        Bs[0][sidx][d4 + 1] = __uint_as_float(cvt_tf32(bv.y));
        Bs[0][sidx][d4 + 2] = __uint_as_float(cvt_tf32(bv.z));
        Bs[0][sidx][d4 + 3] = __uint_as_float(cvt_tf32(bv.w));
    }
    __syncthreads();

    const int NC = S_ / 16;   // 128
    int buf = 0;
    for (int kc = 0; kc < NC; kc++) {
        const bool more = (kc + 1) < NC;
        float4 a0r, a1r, bvr;
        if (more) {
            a0r = *(float4*)(Pr + (kc + 1) * 16);
            a1r = *(float4*)(Pr + (kc + 1) * 16 + 4);
            bvr = *(const float4*)(Vb + (size_t)((kc + 1) * 16 + sidx) * E_ + d4);
        }
#pragma unroll
        for (int kt = 0; kt < 2; kt++) {
            const int kk = kt * 8;
            unsigned af[2][4], bf[4][2];
#pragma unroll
            for (int i = 0; i < 2; i++) {
                int mb = wm * 32 + i * 16 + lr;
                af[i][0] = __float_as_uint(As[buf][kk + lc][mb]);
                af[i][1] = __float_as_uint(As[buf][kk + lc][mb + 8]);
                af[i][2] = __float_as_uint(As[buf][kk + 4 + lc][mb]);
                af[i][3] = __float_as_uint(As[buf][kk + 4 + lc][mb + 8]);
            }
#pragma unroll
            for (int j = 0; j < 4; j++) {
                int nbx = wn * 32 + j * 8 + lr;
                bf[j][0] = __float_as_uint(Bs[buf][kk + lc][nbx]);
                bf[j][1] = __float_as_uint(Bs[buf][kk + 4 + lc][nbx]);
            }
#pragma unroll
            for (int i = 0; i < 2; i++)
#pragma unroll
                for (int j = 0; j < 4; j++)
                    mma8(acc[i][j], af[i], bf[j]);
        }
        if (more) {
            buf ^= 1;
            a0r.x = __expf(a0r.x - mrow) * inv;
            a0r.y = __expf(a0r.y - mrow) * inv;
            a0r.z = __expf(a0r.z - mrow) * inv;
            a0r.w = __expf(a0r.w - mrow) * inv;
            a1r.x = __expf(a1r.x - mrow) * inv;
            a1r.y = __expf(a1r.y - mrow) * inv;
            a1r.z = __expf(a1r.z - mrow) * inv;
            a1r.w = __expf(a1r.w - mrow) * inv;
            *(float4*)(Pr + (kc + 1) * 16)     = a0r;
            *(float4*)(Pr + (kc + 1) * 16 + 4) = a1r;
            As[buf][ak + 0][arow] = __uint_as_float(cvt_tf32(a0r.x));
            As[buf][ak + 1][arow] = __uint_as_float(cvt_tf32(a0r.y));
            As[buf][ak + 2][arow] = __uint_as_float(cvt_tf32(a0r.z));
            As[buf][ak + 3][arow] = __uint_as_float(cvt_tf32(a0r.w));
            As[buf][ak + 4][arow] = __uint_as_float(cvt_tf32(a1r.x));
            As[buf][ak + 5][arow] = __uint_as_float(cvt_tf32(a1r.y));
            As[buf][ak + 6][arow] = __uint_as_float(cvt_tf32(a1r.z));
            As[buf][ak + 7][arow] = __uint_as_float(cvt_tf32(a1r.w));
            Bs[buf][sidx][d4 + 0] = __uint_as_float(cvt_tf32(bvr.x));
            Bs[buf][sidx][d4 + 1] = __uint_as_float(cvt_tf32(bvr.y));
            Bs[buf][sidx][d4 + 2] = __uint_as_float(cvt_tf32(bvr.z));
            Bs[buf][sidx][d4 + 3] = __uint_as_float(cvt_tf32(bvr.w));
            __syncthreads();
        }
    }

#pragma unroll
    for (int j = 0; j < 4; j++) {
        int col = wn * 32 + j * 8 + lc * 2;
#pragma unroll
        for (int i = 0; i < 2; i++) {
            int row = bm + wm * 32 + i * 16 + lr;
            *(float2*)(C + (size_t)row * E_ + col)       = make_float2(acc[i][j][0], acc[i][j][1]);
            *(float2*)(C + (size_t)(row + 8) * E_ + col) = make_float2(acc[i][j][2], acc[i][j][3]);
        }
    }
}

// ---------------------------------------------------------------------------
extern "C" void kernel_launch(void* const* d_in, const int* in_sizes, int n_in,
                              void* d_out, int out_size)
{
    const float* q    = (const float*)d_in[0];
    const float* k    = (const float*)d_in[1];
    const float* v    = (const float*)d_in[2];
    const int*   mask = (const int*)d_in[3];
    const float* Wq   = (const float*)d_in[4];
    const float* bq   = (const float*)d_in[5];
    const float* Wk   = (const float*)d_in[6];
    const float* bk   = (const float*)d_in[7];
    const float* Wv   = (const float*)d_in[8];
    const float* bv   = (const float*)d_in[9];
    const float* Wo   = (const float*)d_in[10];
    const float* bo   = (const float*)d_in[11];

    float* out  = (float*)d_out;
    float* attn = out + (size_t)B_ * T_ * E_;

    float *Qp, *Kp, *Vp, *Ctx;
    float2 *part;
    cudaGetSymbolAddress((void**)&Qp, g_Qp);
    cudaGetSymbolAddress((void**)&Kp, g_Kp);
    cudaGetSymbolAddress((void**)&Vp, g_Vp);
    cudaGetSymbolAddress((void**)&Ctx, g_ctx);
    cudaGetSymbolAddress((void**)&part, g_part);

    dim3 gproj(E_ / 128, (B_ * T_) / 128);   // (8, 32)

    gemm_nt_bias<<<gproj, 512>>>(q, Wq, bq, Qp, E_, E_, E_, E_, SCALE_);
    gemm_nt_bias<<<gproj, 512>>>(k, Wk, bk, Kp, E_, E_, E_, E_, 1.0f);
    gemm_nt_bias<<<gproj, 512>>>(v, Wv, bv, Vp, E_, E_, E_, E_, 1.0f);

    attn_scores<<<dim3(S_ / 128, T_ / 128, B_ * H_), 512>>>(Qp, Kp, mask, attn, part);

    attn_pv<<<dim3(T_ / 128, B_ * H_), 256>>>(attn, Vp, part, Ctx);

    gemm_nt_bias<<<gproj, 512>>>(Ctx, Wo, bo, out, E_, E_, E_, E_, 1.0f);
}

// round 6
// speedup vs baseline: 1.2984x; 1.2984x over previous
#include <cuda_runtime.h>
#include <math.h>

#define B_   2
#define T_   2048
#define S_   2048
#define E_   1024
#define H_   16
#define DH_  64
#define SCALE_ 0.125f
#define CLAMP_V 50000.0f
#define NBLK 16              // S_/128 score col-blocks per row

// Scratch (device globals: no allocations allowed)
__device__ float  g_Qp[B_ * T_ * E_];
__device__ float  g_Kp[B_ * S_ * E_];
__device__ float  g_Vp[B_ * S_ * E_];
__device__ float  g_ctx[B_ * T_ * E_];
__device__ float2 g_part[(size_t)B_ * H_ * T_ * NBLK];

// ---------------------------------------------------------------------------
__device__ __forceinline__ unsigned cvt_tf32(float x) {
    unsigned r;
    asm("cvt.rna.tf32.f32 %0, %1;" : "=r"(r) : "f"(x));
    return r;
}

__device__ __forceinline__ void mma8(float* d, const unsigned* a, const unsigned* b) {
    asm volatile(
        "mma.sync.aligned.m16n8k8.row.col.f32.tf32.tf32.f32 "
        "{%0,%1,%2,%3}, {%4,%5,%6,%7}, {%8,%9}, {%0,%1,%2,%3};"
        : "+f"(d[0]), "+f"(d[1]), "+f"(d[2]), "+f"(d[3])
        : "r"(a[0]), "r"(a[1]), "r"(a[2]), "r"(a[3]), "r"(b[0]), "r"(b[1]));
}

__device__ __forceinline__ void softmax_merge(float& m, float& s, float om, float os) {
    float nm = fmaxf(m, om);
    if (nm == -INFINITY) { m = nm; s = 0.f; return; }
    s = s * __expf(m - nm) + os * __expf(om - nm);
    m = nm;
}

// store 16 k-consecutive tf32 values k-major: Sm[k..k+15][row]
#define STG16(Sm, row, v0, v1, v2, v3)                                     \
    do {                                                                   \
        Sm[0][row]  = __uint_as_float(cvt_tf32((v0).x));                   \
        Sm[1][row]  = __uint_as_float(cvt_tf32((v0).y));                   \
        Sm[2][row]  = __uint_as_float(cvt_tf32((v0).z));                   \
        Sm[3][row]  = __uint_as_float(cvt_tf32((v0).w));                   \
        Sm[4][row]  = __uint_as_float(cvt_tf32((v1).x));                   \
        Sm[5][row]  = __uint_as_float(cvt_tf32((v1).y));                   \
        Sm[6][row]  = __uint_as_float(cvt_tf32((v1).z));                   \
        Sm[7][row]  = __uint_as_float(cvt_tf32((v1).w));                   \
        Sm[8][row]  = __uint_as_float(cvt_tf32((v2).x));                   \
        Sm[9][row]  = __uint_as_float(cvt_tf32((v2).y));                   \
        Sm[10][row] = __uint_as_float(cvt_tf32((v2).z));                   \
        Sm[11][row] = __uint_as_float(cvt_tf32((v2).w));                   \
        Sm[12][row] = __uint_as_float(cvt_tf32((v3).x));                   \
        Sm[13][row] = __uint_as_float(cvt_tf32((v3).y));                   \
        Sm[14][row] = __uint_as_float(cvt_tf32((v3).z));                   \
        Sm[15][row] = __uint_as_float(cvt_tf32((v3).w));                   \
    } while (0)

// Per-k8 fragment load + 4x8 mma, warp tile 64x64.
// As/Bs: [16][pad] k-major. mbase/nbase: warp row/col offsets.
#define K8_MMA(As, Bs, padA, padB, kk, mbase, nbase, acc)                  \
    do {                                                                   \
        unsigned af[4][4], bf[8][2];                                       \
        _Pragma("unroll")                                                  \
        for (int i = 0; i < 4; i++) {                                      \
            int mb = (mbase) + i * 16 + lr;                                \
            af[i][0] = __float_as_uint((As)[(kk) + lc][mb]);               \
            af[i][1] = __float_as_uint((As)[(kk) + lc][mb + 8]);           \
            af[i][2] = __float_as_uint((As)[(kk) + 4 + lc][mb]);           \
            af[i][3] = __float_as_uint((As)[(kk) + 4 + lc][mb + 8]);       \
        }                                                                  \
        _Pragma("unroll")                                                  \
        for (int j = 0; j < 8; j++) {                                      \
            int nb = (nbase) + j * 8 + lr;                                 \
            bf[j][0] = __float_as_uint((Bs)[(kk) + lc][nb]);               \
            bf[j][1] = __float_as_uint((Bs)[(kk) + 4 + lc][nb]);           \
        }                                                                  \
        _Pragma("unroll")                                                  \
        for (int i = 0; i < 4; i++)                                        \
            _Pragma("unroll")                                              \
            for (int j = 0; j < 8; j++)                                    \
                mma8(acc[i][j], af[i], bf[j]);                             \
    } while (0)

// ---------------------------------------------------------------------------
// NT GEMM + bias + alpha, tf32 mma.sync.  BM=BN=128, BK=16, 128 threads,
// 4 warps in 2x2 grid, warp tile 64x64, double-buffered smem.
// ---------------------------------------------------------------------------
__global__ __launch_bounds__(128) void gemm_nt_bias(
    const float* __restrict__ A, const float* __restrict__ Bm,
    const float* __restrict__ bias, float* __restrict__ C,
    int K, int lda, int ldb, int ldc, float alpha)
{
    __shared__ float As[2][16][136];
    __shared__ float Bs[2][16][136];
    const int tid = threadIdx.x;
    const int lane = tid & 31, w = tid >> 5;
    const int wm = w & 1, wn = w >> 1;
    const int lr = lane >> 2, lc = lane & 3;
    const int bm = blockIdx.y * 128, bn = blockIdx.x * 128;

    const float* Ap = A + (size_t)(bm + tid) * lda;
    const float* Bp = Bm + (size_t)(bn + tid) * ldb;

    float acc[4][8][4] = {};

    {
        float4 a0 = *(const float4*)(Ap);
        float4 a1 = *(const float4*)(Ap + 4);
        float4 a2 = *(const float4*)(Ap + 8);
        float4 a3 = *(const float4*)(Ap + 12);
        STG16(As[0], tid, a0, a1, a2, a3);
        float4 b0 = *(const float4*)(Bp);
        float4 b1 = *(const float4*)(Bp + 4);
        float4 b2 = *(const float4*)(Bp + 8);
        float4 b3 = *(const float4*)(Bp + 12);
        STG16(Bs[0], tid, b0, b1, b2, b3);
    }
    __syncthreads();

    const int NC = K >> 4;
    int buf = 0;
    for (int kc = 0; kc < NC; kc++) {
        const bool more = (kc + 1) < NC;
        float4 na0, na1, na2, na3, nb0, nb1, nb2, nb3;
        if (more) {
            const float* ap = Ap + (kc + 1) * 16;
            const float* bp = Bp + (kc + 1) * 16;
            na0 = *(const float4*)(ap);      na1 = *(const float4*)(ap + 4);
            na2 = *(const float4*)(ap + 8);  na3 = *(const float4*)(ap + 12);
            nb0 = *(const float4*)(bp);      nb1 = *(const float4*)(bp + 4);
            nb2 = *(const float4*)(bp + 8);  nb3 = *(const float4*)(bp + 12);
        }
        K8_MMA(As[buf], Bs[buf], 136, 136, 0, wm * 64, wn * 64, acc);
        K8_MMA(As[buf], Bs[buf], 136, 136, 8, wm * 64, wn * 64, acc);
        if (more) {
            buf ^= 1;
            STG16(As[buf], tid, na0, na1, na2, na3);
            STG16(Bs[buf], tid, nb0, nb1, nb2, nb3);
            __syncthreads();
        }
    }

#pragma unroll
    for (int j = 0; j < 8; j++) {
        int col = bn + wn * 64 + j * 8 + lc * 2;
        float b0v = bias[col], b1v = bias[col + 1];
#pragma unroll
        for (int i = 0; i < 4; i++) {
            int row = bm + wm * 64 + i * 16 + lr;
            *(float2*)(C + (size_t)row * ldc + col) =
                make_float2(alpha * (acc[i][j][0] + b0v), alpha * (acc[i][j][1] + b1v));
            *(float2*)(C + (size_t)(row + 8) * ldc + col) =
                make_float2(alpha * (acc[i][j][2] + b0v), alpha * (acc[i][j][3] + b1v));
        }
    }
}

// ---------------------------------------------------------------------------
// Scores: per (b,h) 128x128 tile of clamp(Q.K^T) + mask -> -inf, raw store,
// per-(row, colblock) softmax partials.  K=64 (4 chunks).  128 threads.
// ---------------------------------------------------------------------------
__global__ __launch_bounds__(128) void attn_scores(
    const float* __restrict__ Qp, const float* __restrict__ Kp,
    const int* __restrict__ mask, float* __restrict__ P,
    float2* __restrict__ part)
{
    __shared__ float As[2][16][136];
    __shared__ float Bs[2][16][136];
    __shared__ float2 red[2][128];
    __shared__ int msk[128];

    const int bh = blockIdx.z, b = bh >> 4, h = bh & 15;
    float* C = P + (size_t)bh * T_ * S_;

    const int tid = threadIdx.x;
    const int lane = tid & 31, w = tid >> 5;
    const int wm = w & 1, wn = w >> 1;
    const int lr = lane >> 2, lc = lane & 3;
    const int bm = blockIdx.y * 128, bn = blockIdx.x * 128;

    const float* Ap = Qp + (size_t)b * T_ * E_ + (size_t)(bm + tid) * E_ + h * DH_;
    const float* Bp = Kp + (size_t)b * S_ * E_ + (size_t)(bn + tid) * E_ + h * DH_;

    float acc[4][8][4] = {};

    msk[tid] = mask[(size_t)b * S_ + bn + tid];
    {
        float4 a0 = *(const float4*)(Ap);
        float4 a1 = *(const float4*)(Ap + 4);
        float4 a2 = *(const float4*)(Ap + 8);
        float4 a3 = *(const float4*)(Ap + 12);
        STG16(As[0], tid, a0, a1, a2, a3);
        float4 b0 = *(const float4*)(Bp);
        float4 b1 = *(const float4*)(Bp + 4);
        float4 b2 = *(const float4*)(Bp + 8);
        float4 b3 = *(const float4*)(Bp + 12);
        STG16(Bs[0], tid, b0, b1, b2, b3);
    }
    __syncthreads();

    int buf = 0;
#pragma unroll
    for (int kc = 0; kc < 4; kc++) {
        const bool more = kc < 3;
        float4 na0, na1, na2, na3, nb0, nb1, nb2, nb3;
        if (more) {
            const float* ap = Ap + (kc + 1) * 16;
            const float* bp = Bp + (kc + 1) * 16;
            na0 = *(const float4*)(ap);      na1 = *(const float4*)(ap + 4);
            na2 = *(const float4*)(ap + 8);  na3 = *(const float4*)(ap + 12);
            nb0 = *(const float4*)(bp);      nb1 = *(const float4*)(bp + 4);
            nb2 = *(const float4*)(bp + 8);  nb3 = *(const float4*)(bp + 12);
        }
        K8_MMA(As[buf], Bs[buf], 136, 136, 0, wm * 64, wn * 64, acc);
        K8_MMA(As[buf], Bs[buf], 136, 136, 8, wm * 64, wn * 64, acc);
        if (more) {
            buf ^= 1;
            STG16(As[buf], tid, na0, na1, na2, na3);
            STG16(Bs[buf], tid, nb0, nb1, nb2, nb3);
            __syncthreads();
        }
    }

    // epilogue: clamp + mask + raw store + per-row (m,s)
#pragma unroll
    for (int i = 0; i < 4; i++) {
        int rl = wm * 64 + i * 16 + lr;
        float vlo[16], vhi[16];
        float m_lo = -INFINITY, m_hi = -INFINITY;
#pragma unroll
        for (int j = 0; j < 8; j++) {
            int lcol = wn * 64 + j * 8 + lc * 2;
            bool k0 = msk[lcol] != 0, k1 = msk[lcol + 1] != 0;
            float a0 = fminf(fmaxf(acc[i][j][0], -CLAMP_V), CLAMP_V);
            float a1 = fminf(fmaxf(acc[i][j][1], -CLAMP_V), CLAMP_V);
            float a2 = fminf(fmaxf(acc[i][j][2], -CLAMP_V), CLAMP_V);
            float a3 = fminf(fmaxf(acc[i][j][3], -CLAMP_V), CLAMP_V);
            vlo[j * 2]     = k0 ? a0 : -INFINITY;
            vlo[j * 2 + 1] = k1 ? a1 : -INFINITY;
            vhi[j * 2]     = k0 ? a2 : -INFINITY;
            vhi[j * 2 + 1] = k1 ? a3 : -INFINITY;
            m_lo = fmaxf(m_lo, fmaxf(vlo[j * 2], vlo[j * 2 + 1]));
            m_hi = fmaxf(m_hi, fmaxf(vhi[j * 2], vhi[j * 2 + 1]));
            int col = bn + lcol;
            *(float2*)(C + (size_t)(bm + rl) * S_ + col)     = make_float2(vlo[j * 2], vlo[j * 2 + 1]);
            *(float2*)(C + (size_t)(bm + rl + 8) * S_ + col) = make_float2(vhi[j * 2], vhi[j * 2 + 1]);
        }
        float s_lo = 0.f, s_hi = 0.f;
        if (m_lo != -INFINITY) {
#pragma unroll
            for (int u = 0; u < 16; u++) s_lo += __expf(vlo[u] - m_lo);
        }
        if (m_hi != -INFINITY) {
#pragma unroll
            for (int u = 0; u < 16; u++) s_hi += __expf(vhi[u] - m_hi);
        }
#pragma unroll
        for (int off = 1; off <= 2; off <<= 1) {
            softmax_merge(m_lo, s_lo, __shfl_xor_sync(0xffffffffu, m_lo, off),
                                      __shfl_xor_sync(0xffffffffu, s_lo, off));
            softmax_merge(m_hi, s_hi, __shfl_xor_sync(0xffffffffu, m_hi, off),
                                      __shfl_xor_sync(0xffffffffu, s_hi, off));
        }
        if (lc == 0) {
            red[wn][rl]     = make_float2(m_lo, s_lo);
            red[wn][rl + 8] = make_float2(m_hi, s_hi);
        }
    }
    __syncthreads();
    {
        float2 p0 = red[0][tid], p1 = red[1][tid];
        float m = p0.x, s = p0.y;
        softmax_merge(m, s, p1.x, p1.y);
        part[((size_t)bh * T_ + bm + tid) * NBLK + blockIdx.x] = make_float2(m, s);
    }
}

// ---------------------------------------------------------------------------
// PV: merges per-row stats from partials (registers only), reads raw scores,
// p = exp(v-m)*inv, writes normalized P back, Ctx = P @ V.
// BM=256, BN=64, BK=16, 128 threads, 4 warps stacked on M, warp tile 64x64.
// ---------------------------------------------------------------------------
__global__ __launch_bounds__(128) void attn_pv(
    float* __restrict__ P, const float* __restrict__ Vp,
    const float2* __restrict__ part, float* __restrict__ Ctx)
{
    __shared__ float As[2][16][264];
    __shared__ float Bs[2][16][72];

    const int bh = blockIdx.y, b = bh >> 4, h = bh & 15;
    float* A = P + (size_t)bh * T_ * S_;
    const float* Vb = Vp + (size_t)b * S_ * E_ + h * DH_;
    float* C = Ctx + (size_t)b * T_ * E_ + h * DH_;

    const int tid = threadIdx.x;
    const int lane = tid & 31, w = tid >> 5;
    const int lr = lane >> 2, lc = lane & 3;
    const int bm = blockIdx.x * 256;

    // rows this thread stages: tid and tid+128.  Merge their stats (registers).
    float mr0 = -INFINITY, sr0 = 0.f, mr1 = -INFINITY, sr1 = 0.f;
#pragma unroll
    for (int j = 0; j < NBLK; j++) {
        float2 p0 = part[((size_t)bh * T_ + bm + tid) * NBLK + j];
        float2 p1 = part[((size_t)bh * T_ + bm + tid + 128) * NBLK + j];
        softmax_merge(mr0, sr0, p0.x, p0.y);
        softmax_merge(mr1, sr1, p1.x, p1.y);
    }
    const float inv0 = 1.f / sr0, inv1 = 1.f / sr1;

    float* Pr0 = A + (size_t)(bm + tid) * S_;
    float* Pr1 = A + (size_t)(bm + tid + 128) * S_;
    const int srow = tid >> 3, dcol = (tid & 7) * 8;   // B loader: 16 x 64

    float acc[4][8][4] = {};

#define PV_STAGE_A(dst, Pr, mrow, inv, row)                                \
    do {                                                                   \
        float4 x0 = *(float4*)(Pr);                                        \
        float4 x1 = *(float4*)((Pr) + 4);                                  \
        float4 x2 = *(float4*)((Pr) + 8);                                  \
        float4 x3 = *(float4*)((Pr) + 12);                                 \
        x0.x = __expf(x0.x - (mrow)) * (inv);                              \
        x0.y = __expf(x0.y - (mrow)) * (inv);                              \
        x0.z = __expf(x0.z - (mrow)) * (inv);                              \
        x0.w = __expf(x0.w - (mrow)) * (inv);                              \
        x1.x = __expf(x1.x - (mrow)) * (inv);                              \
        x1.y = __expf(x1.y - (mrow)) * (inv);                              \
        x1.z = __expf(x1.z - (mrow)) * (inv);                              \
        x1.w = __expf(x1.w - (mrow)) * (inv);                              \
        x2.x = __expf(x2.x - (mrow)) * (inv);                              \
        x2.y = __expf(x2.y - (mrow)) * (inv);                              \
        x2.z = __expf(x2.z - (mrow)) * (inv);                              \
        x2.w = __expf(x2.w - (mrow)) * (inv);                              \
        x3.x = __expf(x3.x - (mrow)) * (inv);                              \
        x3.y = __expf(x3.y - (mrow)) * (inv);                              \
        x3.z = __expf(x3.z - (mrow)) * (inv);                              \
        x3.w = __expf(x3.w - (mrow)) * (inv);                              \
        *(float4*)(Pr)      = x0;                                          \
        *(float4*)((Pr) + 4)  = x1;                                        \
        *(float4*)((Pr) + 8)  = x2;                                        \
        *(float4*)((Pr) + 12) = x3;                                        \
        STG16(dst, row, x0, x1, x2, x3);                                   \
    } while (0)

#define PV_STAGE_B(dst, koff)                                              \
    do {                                                                   \
        float4 v0 = *(const float4*)(Vb + (size_t)((koff) + srow) * E_ + dcol);     \
        float4 v1 = *(const float4*)(Vb + (size_t)((koff) + srow) * E_ + dcol + 4); \
        dst[srow][dcol + 0] = __uint_as_float(cvt_tf32(v0.x));             \
        dst[srow][dcol + 1] = __uint_as_float(cvt_tf32(v0.y));             \
        dst[srow][dcol + 2] = __uint_as_float(cvt_tf32(v0.z));             \
        dst[srow][dcol + 3] = __uint_as_float(cvt_tf32(v0.w));             \
        dst[srow][dcol + 4] = __uint_as_float(cvt_tf32(v1.x));             \
        dst[srow][dcol + 5] = __uint_as_float(cvt_tf32(v1.y));             \
        dst[srow][dcol + 6] = __uint_as_float(cvt_tf32(v1.z));             \
        dst[srow][dcol + 7] = __uint_as_float(cvt_tf32(v1.w));             \
    } while (0)

    PV_STAGE_A(As[0], Pr0, mr0, inv0, tid);
    PV_STAGE_A(As[0], Pr1, mr1, inv1, tid + 128);
    PV_STAGE_B(Bs[0], 0);
    __syncthreads();

    const int NC = S_ / 16;   // 128
    int buf = 0;
    for (int kc = 0; kc < NC; kc++) {
        const bool more = (kc + 1) < NC;
        K8_MMA(As[buf], Bs[buf], 264, 72, 0, w * 64, 0, acc);
        K8_MMA(As[buf], Bs[buf], 264, 72, 8, w * 64, 0, acc);
        if (more) {
            buf ^= 1;
            PV_STAGE_A(As[buf], Pr0 + (kc + 1) * 16, mr0, inv0, tid);
            PV_STAGE_A(As[buf], Pr1 + (kc + 1) * 16, mr1, inv1, tid + 128);
            PV_STAGE_B(Bs[buf], (kc + 1) * 16);
            __syncthreads();
        }
    }

#pragma unroll
    for (int j = 0; j < 8; j++) {
        int col = j * 8 + lc * 2;
#pragma unroll
        for (int i = 0; i < 4; i++) {
            int row = bm + w * 64 + i * 16 + lr;
            *(float2*)(C + (size_t)row * E_ + col)       = make_float2(acc[i][j][0], acc[i][j][1]);
            *(float2*)(C + (size_t)(row + 8) * E_ + col) = make_float2(acc[i][j][2], acc[i][j][3]);
        }
    }
#undef PV_STAGE_A
#undef PV_STAGE_B
}

// ---------------------------------------------------------------------------
extern "C" void kernel_launch(void* const* d_in, const int* in_sizes, int n_in,
                              void* d_out, int out_size)
{
    const float* q    = (const float*)d_in[0];
    const float* k    = (const float*)d_in[1];
    const float* v    = (const float*)d_in[2];
    const int*   mask = (const int*)d_in[3];
    const float* Wq   = (const float*)d_in[4];
    const float* bq   = (const float*)d_in[5];
    const float* Wk   = (const float*)d_in[6];
    const float* bk   = (const float*)d_in[7];
    const float* Wv   = (const float*)d_in[8];
    const float* bv   = (const float*)d_in[9];
    const float* Wo   = (const float*)d_in[10];
    const float* bo   = (const float*)d_in[11];

    float* out  = (float*)d_out;
    float* attn = out + (size_t)B_ * T_ * E_;

    float *Qp, *Kp, *Vp, *Ctx;
    float2 *part;
    cudaGetSymbolAddress((void**)&Qp, g_Qp);
    cudaGetSymbolAddress((void**)&Kp, g_Kp);
    cudaGetSymbolAddress((void**)&Vp, g_Vp);
    cudaGetSymbolAddress((void**)&Ctx, g_ctx);
    cudaGetSymbolAddress((void**)&part, g_part);

    dim3 gproj(E_ / 128, (B_ * T_) / 128);   // (8, 32)

    gemm_nt_bias<<<gproj, 128>>>(q, Wq, bq, Qp, E_, E_, E_, E_, SCALE_);
    gemm_nt_bias<<<gproj, 128>>>(k, Wk, bk, Kp, E_, E_, E_, E_, 1.0f);
    gemm_nt_bias<<<gproj, 128>>>(v, Wv, bv, Vp, E_, E_, E_, E_, 1.0f);

    attn_scores<<<dim3(S_ / 128, T_ / 128, B_ * H_), 128>>>(Qp, Kp, mask, attn, part);

    attn_pv<<<dim3(T_ / 256, B_ * H_), 128>>>(attn, Vp, part, Ctx);

    gemm_nt_bias<<<gproj, 128>>>(Ctx, Wo, bo, out, E_, E_, E_, E_, 1.0f);
}

// round 8
// speedup vs baseline: 1.6084x; 1.2387x over previous
#include <cuda_runtime.h>
#include <math.h>

#define B_   2
#define T_   2048
#define S_   2048
#define E_   1024
#define H_   16
#define DH_  64
#define SCALE_ 0.125f
#define CLAMP_V 50000.0f
#define NBLK 16              // S_/128 score col-blocks per row

// Scratch (device globals: no allocations allowed)
__device__ float  g_Qp[B_ * T_ * E_];
__device__ float  g_Kp[B_ * S_ * E_];
__device__ float  g_Vp[B_ * S_ * E_];
__device__ float  g_ctx[B_ * T_ * E_];
__device__ float2 g_part[(size_t)B_ * H_ * T_ * NBLK];

// ---------------------------------------------------------------------------
__device__ __forceinline__ unsigned smem_u32(const void* p) {
    unsigned r;
    asm("{ .reg .u64 t; cvta.to.shared.u64 t, %1; cvt.u32.u64 %0, t; }"
        : "=r"(r) : "l"(p));
    return r;
}

#define CP16(d, s) \
    asm volatile("cp.async.cg.shared.global [%0], [%1], 16;" :: "r"(d), "l"(s))
#define CP_COMMIT() asm volatile("cp.async.commit_group;" ::: "memory")
#define CP_WAIT(n)  asm volatile("cp.async.wait_group %0;" :: "n"(n) : "memory")

__device__ __forceinline__ unsigned cvt_tf32(float x) {
    unsigned r;
    asm("cvt.rna.tf32.f32 %0, %1;" : "=r"(r) : "f"(x));
    return r;
}

__device__ __forceinline__ void mma8(float* d, const unsigned* a, const unsigned* b) {
    asm volatile(
        "mma.sync.aligned.m16n8k8.row.col.f32.tf32.tf32.f32 "
        "{%0,%1,%2,%3}, {%4,%5,%6,%7}, {%8,%9}, {%0,%1,%2,%3};"
        : "+f"(d[0]), "+f"(d[1]), "+f"(d[2]), "+f"(d[3])
        : "r"(a[0]), "r"(a[1]), "r"(a[2]), "r"(a[3]), "r"(b[0]), "r"(b[1]));
}

__device__ __forceinline__ void softmax_merge(float& m, float& s, float om, float os) {
    float nm = fmaxf(m, om);
    if (nm == -INFINITY) { m = nm; s = 0.f; return; }
    s = s * __expf(m - nm) + os * __expf(om - nm);
    m = nm;
}

// Fragment compute from RAW row-major smem (pad 20), cvt at load. 64x32 warp tile.
#define K8_RAW(As_, Bs_, kk, mbase, nbase, acc)                            \
    do {                                                                   \
        unsigned af[4][4], bf[4][2];                                       \
        _Pragma("unroll")                                                  \
        for (int i = 0; i < 4; i++) {                                      \
            int mr = (mbase) + i * 16 + lr;                                \
            af[i][0] = cvt_tf32((As_)[mr][(kk) + lc]);                     \
            af[i][1] = cvt_tf32((As_)[mr + 8][(kk) + lc]);                 \
            af[i][2] = cvt_tf32((As_)[mr][(kk) + 4 + lc]);                 \
            af[i][3] = cvt_tf32((As_)[mr + 8][(kk) + 4 + lc]);             \
        }                                                                  \
        _Pragma("unroll")                                                  \
        for (int j = 0; j < 4; j++) {                                      \
            int nr = (nbase) + j * 8 + lr;                                 \
            bf[j][0] = cvt_tf32((Bs_)[nr][(kk) + lc]);                     \
            bf[j][1] = cvt_tf32((Bs_)[nr][(kk) + 4 + lc]);                 \
        }                                                                  \
        _Pragma("unroll")                                                  \
        for (int i = 0; i < 4; i++)                                        \
            _Pragma("unroll")                                              \
            for (int j = 0; j < 4; j++)                                    \
                mma8(acc[i][j], af[i], bf[j]);                             \
    } while (0)

// store 8 k-consecutive tf32 values k-major: Sm[k..k+7][row] (PV A staging)
__device__ __forceinline__ void stg8(float (*Sm)[136], int kb, int row,
                                     float4 v0, float4 v1) {
    Sm[kb + 0][row] = __uint_as_float(cvt_tf32(v0.x));
    Sm[kb + 1][row] = __uint_as_float(cvt_tf32(v0.y));
    Sm[kb + 2][row] = __uint_as_float(cvt_tf32(v0.z));
    Sm[kb + 3][row] = __uint_as_float(cvt_tf32(v0.w));
    Sm[kb + 4][row] = __uint_as_float(cvt_tf32(v1.x));
    Sm[kb + 5][row] = __uint_as_float(cvt_tf32(v1.y));
    Sm[kb + 6][row] = __uint_as_float(cvt_tf32(v1.z));
    Sm[kb + 7][row] = __uint_as_float(cvt_tf32(v1.w));
}

struct GemmArgs {
    const float* A[3];
    const float* W[3];
    const float* bias[3];
    float*       C[3];
    float        alpha[3];
};

// ---------------------------------------------------------------------------
// NT GEMM + bias + alpha.  BM=BN=128, BK=16, 256 thr, 8 warps (2m x 4n),
// warp tile 64x32.  cp.async 2-stage staging, raw fp32 smem (pad 20).
// blockIdx.z selects the (A, W, bias, C, alpha) set.
// ---------------------------------------------------------------------------
__global__ __launch_bounds__(256) void gemm_nt_bias(
    GemmArgs ga, int K, int lda, int ldb, int ldc)
{
    const int z = blockIdx.z;
    const float* A    = ga.A[z];
    const float* Bm   = ga.W[z];
    const float* bias = ga.bias[z];
    float*       C    = ga.C[z];
    const float  alpha = ga.alpha[z];

    __shared__ float As[2][128][20];
    __shared__ float Bs[2][128][20];

    const int tid = threadIdx.x;
    const int lane = tid & 31, w = tid >> 5;
    const int wm = w & 1, wn = w >> 1;
    const int lr = lane >> 2, lc = lane & 3;
    const int bm = blockIdx.y * 128, bn = blockIdx.x * 128;
    const int row = tid >> 1, half = tid & 1;

    const float* Ag = A + (size_t)(bm + row) * lda + half * 8;
    const float* Bg = Bm + (size_t)(bn + row) * ldb + half * 8;
    const unsigned daBase = smem_u32(&As[0][row][half * 8]);
    const unsigned dbBase = smem_u32(&Bs[0][row][half * 8]);
    const unsigned bufStride = 128 * 20 * 4;

#define G_STAGE(kc, buf)                                                   \
    do {                                                                   \
        unsigned da = daBase + (buf) * bufStride;                          \
        unsigned db = dbBase + (buf) * bufStride;                          \
        CP16(da,      Ag + (kc) * 16);                                     \
        CP16(da + 16, Ag + (kc) * 16 + 4);                                 \
        CP16(db,      Bg + (kc) * 16);                                     \
        CP16(db + 16, Bg + (kc) * 16 + 4);                                 \
        CP_COMMIT();                                                       \
    } while (0)

    float acc[4][4][4] = {};

    const int NC = K >> 4;
    G_STAGE(0, 0);
    G_STAGE(1, 1);

    for (int kc = 0; kc < NC; kc++) {
        const int buf = kc & 1;
        if (kc + 1 < NC) CP_WAIT(1); else CP_WAIT(0);
        __syncthreads();
        K8_RAW(As[buf], Bs[buf], 0, wm * 64, wn * 32, acc);
        K8_RAW(As[buf], Bs[buf], 8, wm * 64, wn * 32, acc);
        __syncthreads();
        if (kc + 2 < NC) G_STAGE(kc + 2, buf);
    }
#undef G_STAGE

#pragma unroll
    for (int j = 0; j < 4; j++) {
        int col = bn + wn * 32 + j * 8 + lc * 2;
        float b0v = bias[col], b1v = bias[col + 1];
#pragma unroll
        for (int i = 0; i < 4; i++) {
            int r0 = bm + wm * 64 + i * 16 + lr;
            *(float2*)(C + (size_t)r0 * ldc + col) =
                make_float2(alpha * (acc[i][j][0] + b0v), alpha * (acc[i][j][1] + b1v));
            *(float2*)(C + (size_t)(r0 + 8) * ldc + col) =
                make_float2(alpha * (acc[i][j][2] + b0v), alpha * (acc[i][j][3] + b1v));
        }
    }
}

// ---------------------------------------------------------------------------
// Scores: per (b,h) 128x128 tile: clamp(Q.K^T), mask -> -inf, raw store,
// per-(row, colblock) softmax partials.  K=64 (4 chunks), cp.async staging.
// ---------------------------------------------------------------------------
__global__ __launch_bounds__(256) void attn_scores(
    const float* __restrict__ Qp, const float* __restrict__ Kp,
    const int* __restrict__ mask, float* __restrict__ P,
    float2* __restrict__ part)
{
    __shared__ float As[2][128][20];
    __shared__ float Bs[2][128][20];
    __shared__ float2 red[4][128];
    __shared__ int msk[128];

    const int bh = blockIdx.z, b = bh >> 4, h = bh & 15;
    float* C = P + (size_t)bh * T_ * S_;

    const int tid = threadIdx.x;
    const int lane = tid & 31, w = tid >> 5;
    const int wm = w & 1, wn = w >> 1;
    const int lr = lane >> 2, lc = lane & 3;
    const int bm = blockIdx.y * 128, bn = blockIdx.x * 128;
    const int row = tid >> 1, half = tid & 1;

    const float* Ag = Qp + (size_t)b * T_ * E_ + (size_t)(bm + row) * E_ + h * DH_ + half * 8;
    const float* Bg = Kp + (size_t)b * S_ * E_ + (size_t)(bn + row) * E_ + h * DH_ + half * 8;
    const unsigned daBase = smem_u32(&As[0][row][half * 8]);
    const unsigned dbBase = smem_u32(&Bs[0][row][half * 8]);
    const unsigned bufStride = 128 * 20 * 4;

#define S_STAGE(kc, buf)                                                   \
    do {                                                                   \
        unsigned da = daBase + (buf) * bufStride;                          \
        unsigned db = dbBase + (buf) * bufStride;                          \
        CP16(da,      Ag + (kc) * 16);                                     \
        CP16(da + 16, Ag + (kc) * 16 + 4);                                 \
        CP16(db,      Bg + (kc) * 16);                                     \
        CP16(db + 16, Bg + (kc) * 16 + 4);                                 \
        CP_COMMIT();                                                       \
    } while (0)

    if (tid < 128) msk[tid] = mask[(size_t)b * S_ + bn + tid];

    float acc[4][4][4] = {};

    S_STAGE(0, 0);
    S_STAGE(1, 1);

#pragma unroll
    for (int kc = 0; kc < 4; kc++) {
        const int buf = kc & 1;
        if (kc < 3) CP_WAIT(1); else CP_WAIT(0);
        __syncthreads();
        K8_RAW(As[buf], Bs[buf], 0, wm * 64, wn * 32, acc);
        K8_RAW(As[buf], Bs[buf], 8, wm * 64, wn * 32, acc);
        __syncthreads();
        if (kc < 2) S_STAGE(kc + 2, buf);
    }
#undef S_STAGE

    // epilogue: clamp + mask + raw store + per-row (m,s)
#pragma unroll
    for (int i = 0; i < 4; i++) {
        int rl = wm * 64 + i * 16 + lr;
        float vlo[8], vhi[8];
        float m_lo = -INFINITY, m_hi = -INFINITY;
#pragma unroll
        for (int j = 0; j < 4; j++) {
            int lcol = wn * 32 + j * 8 + lc * 2;
            bool k0 = msk[lcol] != 0, k1 = msk[lcol + 1] != 0;
            float a0 = fminf(fmaxf(acc[i][j][0], -CLAMP_V), CLAMP_V);
            float a1 = fminf(fmaxf(acc[i][j][1], -CLAMP_V), CLAMP_V);
            float a2 = fminf(fmaxf(acc[i][j][2], -CLAMP_V), CLAMP_V);
            float a3 = fminf(fmaxf(acc[i][j][3], -CLAMP_V), CLAMP_V);
            vlo[j * 2]     = k0 ? a0 : -INFINITY;
            vlo[j * 2 + 1] = k1 ? a1 : -INFINITY;
            vhi[j * 2]     = k0 ? a2 : -INFINITY;
            vhi[j * 2 + 1] = k1 ? a3 : -INFINITY;
            m_lo = fmaxf(m_lo, fmaxf(vlo[j * 2], vlo[j * 2 + 1]));
            m_hi = fmaxf(m_hi, fmaxf(vhi[j * 2], vhi[j * 2 + 1]));
            int col = bn + lcol;
            *(float2*)(C + (size_t)(bm + rl) * S_ + col)     = make_float2(vlo[j * 2], vlo[j * 2 + 1]);
            *(float2*)(C + (size_t)(bm + rl + 8) * S_ + col) = make_float2(vhi[j * 2], vhi[j * 2 + 1]);
        }
        float s_lo = 0.f, s_hi = 0.f;
        if (m_lo != -INFINITY) {
#pragma unroll
            for (int u = 0; u < 8; u++) s_lo += __expf(vlo[u] - m_lo);
        }
        if (m_hi != -INFINITY) {
#pragma unroll
            for (int u = 0; u < 8; u++) s_hi += __expf(vhi[u] - m_hi);
        }
#pragma unroll
        for (int off = 1; off <= 2; off <<= 1) {
            softmax_merge(m_lo, s_lo, __shfl_xor_sync(0xffffffffu, m_lo, off),
                                      __shfl_xor_sync(0xffffffffu, s_lo, off));
            softmax_merge(m_hi, s_hi, __shfl_xor_sync(0xffffffffu, m_hi, off),
                                      __shfl_xor_sync(0xffffffffu, s_hi, off));
        }
        if (lc == 0) {
            red[wn][rl]     = make_float2(m_lo, s_lo);
            red[wn][rl + 8] = make_float2(m_hi, s_hi);
        }
    }
    __syncthreads();
    if (tid < 128) {
        float m = -INFINITY, s = 0.f;
#pragma unroll
        for (int j = 0; j < 4; j++) {
            float2 p = red[j][tid];
            softmax_merge(m, s, p.x, p.y);
        }
        part[((size_t)bh * T_ + bm + tid) * NBLK + blockIdx.x] = make_float2(m, s);
    }
}

// ---------------------------------------------------------------------------
// PV: merges row stats from partials, reads raw scores, p = exp(v-m)*inv,
// writes normalized P back, Ctx = P @ V.  BM=128, BN=64, BK=16, 256 thr,
// 8 warps (2m x 4n), warp tile 64x16.  A: reg-staged (transform);
// B (V): cp.async raw k-major (ALL 256 threads cover 16x64 chunk).
// ---------------------------------------------------------------------------
__global__ __launch_bounds__(256) void attn_pv(
    float* __restrict__ P, const float* __restrict__ Vp,
    const float2* __restrict__ part, float* __restrict__ Ctx)
{
    __shared__ float As[2][16][136];   // tf32, k-major
    __shared__ float Bs[2][16][72];    // raw fp32, k-major rows of V
    __shared__ float2 sh_st[128];

    const int bh = blockIdx.y, b = bh >> 4, h = bh & 15;
    float* A = P + (size_t)bh * T_ * S_;
    const float* Vb = Vp + (size_t)b * S_ * E_ + h * DH_;
    float* C = Ctx + (size_t)b * T_ * E_ + h * DH_;

    const int tid = threadIdx.x;
    const int lane = tid & 31, w = tid >> 5;
    const int wm = w & 1, wn = w >> 1;
    const int lr = lane >> 2, lc = lane & 3;
    const int bm = blockIdx.x * 128;

    // merge per-row stats
    if (tid < 128) {
        float m = -INFINITY, s = 0.f;
#pragma unroll
        for (int j = 0; j < NBLK; j++) {
            float2 p = part[((size_t)bh * T_ + bm + tid) * NBLK + j];
            softmax_merge(m, s, p.x, p.y);
        }
        sh_st[tid] = make_float2(m, 1.f / s);
    }
    __syncthreads();

    const int arow = tid >> 1, ak = (tid & 1) * 8;
    float* Pr = A + (size_t)(bm + arow) * S_ + ak;
    const float mrow = sh_st[arow].x, inv = sh_st[arow].y;

    // B loader: 16 rows x 64 floats = 256 cp.16B, one per thread.
    // vrow = tid>>4 (0..15), vseg = tid&15 (0..15) -> cols vseg*4 .. +3.
    const int vrow = tid >> 4, vseg = tid & 15;
    const unsigned dbBase = smem_u32(&Bs[0][vrow][vseg * 4]);
    const unsigned bufStrideB = 16 * 72 * 4;

#define PV_STAGE_B(kc, buf)                                                \
    do {                                                                   \
        CP16(dbBase + (buf) * bufStrideB,                                  \
             Vb + (size_t)((kc) * 16 + vrow) * E_ + vseg * 4);             \
        CP_COMMIT();                                                       \
    } while (0)

    float acc[4][2][4] = {};

    // prologue: A chunk 0 (transform+writeback+STS), B chunks 0,1 (async)
    {
        float4 a0 = *(float4*)(Pr);
        float4 a1 = *(float4*)(Pr + 4);
        a0.x = __expf(a0.x - mrow) * inv;  a0.y = __expf(a0.y - mrow) * inv;
        a0.z = __expf(a0.z - mrow) * inv;  a0.w = __expf(a0.w - mrow) * inv;
        a1.x = __expf(a1.x - mrow) * inv;  a1.y = __expf(a1.y - mrow) * inv;
        a1.z = __expf(a1.z - mrow) * inv;  a1.w = __expf(a1.w - mrow) * inv;
        *(float4*)(Pr)     = a0;
        *(float4*)(Pr + 4) = a1;
        stg8(As[0], ak, arow, a0, a1);
    }
    PV_STAGE_B(0, 0);
    PV_STAGE_B(1, 1);

    const int NC = S_ / 16;   // 128
    for (int kc = 0; kc < NC; kc++) {
        const int buf = kc & 1;
        const bool more = (kc + 1) < NC;
        float4 na0, na1;
        if (more) {
            na0 = *(float4*)(Pr + (kc + 1) * 16);
            na1 = *(float4*)(Pr + (kc + 1) * 16 + 4);
            na0.x = __expf(na0.x - mrow) * inv;  na0.y = __expf(na0.y - mrow) * inv;
            na0.z = __expf(na0.z - mrow) * inv;  na0.w = __expf(na0.w - mrow) * inv;
            na1.x = __expf(na1.x - mrow) * inv;  na1.y = __expf(na1.y - mrow) * inv;
            na1.z = __expf(na1.z - mrow) * inv;  na1.w = __expf(na1.w - mrow) * inv;
            *(float4*)(Pr + (kc + 1) * 16)     = na0;
            *(float4*)(Pr + (kc + 1) * 16 + 4) = na1;
        }
        if (kc + 1 < NC) CP_WAIT(1); else CP_WAIT(0);
        __syncthreads();
        // compute: A tf32 k-major, B raw k-major (cvt at load)
#pragma unroll
        for (int kt = 0; kt < 2; kt++) {
            const int kk = kt * 8;
            unsigned af[4][4], bf[2][2];
#pragma unroll
            for (int i = 0; i < 4; i++) {
                int mb = wm * 64 + i * 16 + lr;
                af[i][0] = __float_as_uint(As[buf][kk + lc][mb]);
                af[i][1] = __float_as_uint(As[buf][kk + lc][mb + 8]);
                af[i][2] = __float_as_uint(As[buf][kk + 4 + lc][mb]);
                af[i][3] = __float_as_uint(As[buf][kk + 4 + lc][mb + 8]);
            }
#pragma unroll
            for (int j = 0; j < 2; j++) {
                int nb = wn * 16 + j * 8 + lr;
                bf[j][0] = cvt_tf32(Bs[buf][kk + lc][nb]);
                bf[j][1] = cvt_tf32(Bs[buf][kk + 4 + lc][nb]);
            }
#pragma unroll
            for (int i = 0; i < 4; i++)
#pragma unroll
                for (int j = 0; j < 2; j++)
                    mma8(acc[i][j], af[i], bf[j]);
        }
        __syncthreads();
        if (more) {
            stg8(As[buf ^ 1], ak, arow, na0, na1);
            if (kc + 2 < NC) PV_STAGE_B(kc + 2, buf);
        }
    }
#undef PV_STAGE_B

#pragma unroll
    for (int j = 0; j < 2; j++) {
        int col = wn * 16 + j * 8 + lc * 2;
#pragma unroll
        for (int i = 0; i < 4; i++) {
            int r0 = bm + wm * 64 + i * 16 + lr;
            *(float2*)(C + (size_t)r0 * E_ + col)       = make_float2(acc[i][j][0], acc[i][j][1]);
            *(float2*)(C + (size_t)(r0 + 8) * E_ + col) = make_float2(acc[i][j][2], acc[i][j][3]);
        }
    }
}

// ---------------------------------------------------------------------------
extern "C" void kernel_launch(void* const* d_in, const int* in_sizes, int n_in,
                              void* d_out, int out_size)
{
    const float* q    = (const float*)d_in[0];
    const float* k    = (const float*)d_in[1];
    const float* v    = (const float*)d_in[2];
    const int*   mask = (const int*)d_in[3];
    const float* Wq   = (const float*)d_in[4];
    const float* bq   = (const float*)d_in[5];
    const float* Wk   = (const float*)d_in[6];
    const float* bk   = (const float*)d_in[7];
    const float* Wv   = (const float*)d_in[8];
    const float* bv   = (const float*)d_in[9];
    const float* Wo   = (const float*)d_in[10];
    const float* bo   = (const float*)d_in[11];

    float* out  = (float*)d_out;
    float* attn = out + (size_t)B_ * T_ * E_;

    float *Qp, *Kp, *Vp, *Ctx;
    float2 *part;
    cudaGetSymbolAddress((void**)&Qp, g_Qp);
    cudaGetSymbolAddress((void**)&Kp, g_Kp);
    cudaGetSymbolAddress((void**)&Vp, g_Vp);
    cudaGetSymbolAddress((void**)&Ctx, g_ctx);
    cudaGetSymbolAddress((void**)&part, g_part);

    dim3 gq(E_ / 128, (B_ * T_) / 128, 3);   // QKV fused: (8, 32, 3)
    GemmArgs g1;
    g1.A[0] = q;  g1.W[0] = Wq; g1.bias[0] = bq; g1.C[0] = Qp; g1.alpha[0] = SCALE_;
    g1.A[1] = k;  g1.W[1] = Wk; g1.bias[1] = bk; g1.C[1] = Kp; g1.alpha[1] = 1.0f;
    g1.A[2] = v;  g1.W[2] = Wv; g1.bias[2] = bv; g1.C[2] = Vp; g1.alpha[2] = 1.0f;
    gemm_nt_bias<<<gq, 256>>>(g1, E_, E_, E_, E_);

    attn_scores<<<dim3(S_ / 128, T_ / 128, B_ * H_), 256>>>(Qp, Kp, mask, attn, part);

    attn_pv<<<dim3(T_ / 128, B_ * H_), 256>>>(attn, Vp, part, Ctx);

    GemmArgs g2;
    g2.A[0] = Ctx; g2.W[0] = Wo; g2.bias[0] = bo; g2.C[0] = out; g2.alpha[0] = 1.0f;
    g2.A[1] = Ctx; g2.W[1] = Wo; g2.bias[1] = bo; g2.C[1] = out; g2.alpha[1] = 1.0f;
    g2.A[2] = Ctx; g2.W[2] = Wo; g2.bias[2] = bo; g2.C[2] = out; g2.alpha[2] = 1.0f;
    gemm_nt_bias<<<dim3(E_ / 128, (B_ * T_) / 128, 1), 256>>>(g2, E_, E_, E_, E_);
}

// round 9
// speedup vs baseline: 1.6409x; 1.0202x over previous
#include <cuda_runtime.h>
#include <math.h>

#define B_   2
#define T_   2048
#define S_   2048
#define E_   1024
#define H_   16
#define DH_  64
#define SCALE_ 0.125f
#define CLAMP_V 50000.0f
#define NBLK 16              // S_/128 score col-blocks per row

// Scratch (device globals: no allocations allowed)
__device__ float  g_Qp[B_ * T_ * E_];
__device__ float  g_Kp[B_ * S_ * E_];
__device__ float  g_Vp[B_ * S_ * E_];
__device__ float  g_ctx[B_ * T_ * E_];
__device__ float2 g_part[(size_t)B_ * H_ * T_ * NBLK];

// ---------------------------------------------------------------------------
__device__ __forceinline__ unsigned smem_u32(const void* p) {
    unsigned r;
    asm("{ .reg .u64 t; cvta.to.shared.u64 t, %1; cvt.u32.u64 %0, t; }"
        : "=r"(r) : "l"(p));
    return r;
}

#define CP16(d, s) \
    asm volatile("cp.async.cg.shared.global [%0], [%1], 16;" :: "r"(d), "l"(s))
#define CP_COMMIT() asm volatile("cp.async.commit_group;" ::: "memory")
#define CP_WAIT(n)  asm volatile("cp.async.wait_group %0;" :: "n"(n) : "memory")

__device__ __forceinline__ unsigned cvt_tf32(float x) {
    unsigned r;
    asm("cvt.rna.tf32.f32 %0, %1;" : "=r"(r) : "f"(x));
    return r;
}

__device__ __forceinline__ void mma8(float* d, const unsigned* a, const unsigned* b) {
    asm volatile(
        "mma.sync.aligned.m16n8k8.row.col.f32.tf32.tf32.f32 "
        "{%0,%1,%2,%3}, {%4,%5,%6,%7}, {%8,%9}, {%0,%1,%2,%3};"
        : "+f"(d[0]), "+f"(d[1]), "+f"(d[2]), "+f"(d[3])
        : "r"(a[0]), "r"(a[1]), "r"(a[2]), "r"(a[3]), "r"(b[0]), "r"(b[1]));
}

__device__ __forceinline__ void softmax_merge(float& m, float& s, float om, float os) {
    float nm = fmaxf(m, om);
    if (nm == -INFINITY) { m = nm; s = 0.f; return; }
    s = s * __expf(m - nm) + os * __expf(om - nm);
    m = nm;
}

// Fragment compute from RAW row-major smem (pad 20), cvt at load. 64x32 warp tile.
#define K8_RAW(As_, Bs_, kk, mbase, nbase, acc)                            \
    do {                                                                   \
        unsigned af[4][4], bf[4][2];                                       \
        _Pragma("unroll")                                                  \
        for (int i = 0; i < 4; i++) {                                      \
            int mr = (mbase) + i * 16 + lr;                                \
            af[i][0] = cvt_tf32((As_)[mr][(kk) + lc]);                     \
            af[i][1] = cvt_tf32((As_)[mr + 8][(kk) + lc]);                 \
            af[i][2] = cvt_tf32((As_)[mr][(kk) + 4 + lc]);                 \
            af[i][3] = cvt_tf32((As_)[mr + 8][(kk) + 4 + lc]);             \
        }                                                                  \
        _Pragma("unroll")                                                  \
        for (int j = 0; j < 4; j++) {                                      \
            int nr = (nbase) + j * 8 + lr;                                 \
            bf[j][0] = cvt_tf32((Bs_)[nr][(kk) + lc]);                     \
            bf[j][1] = cvt_tf32((Bs_)[nr][(kk) + 4 + lc]);                 \
        }                                                                  \
        _Pragma("unroll")                                                  \
        for (int i = 0; i < 4; i++)                                        \
            _Pragma("unroll")                                              \
            for (int j = 0; j < 4; j++)                                    \
                mma8(acc[i][j], af[i], bf[j]);                             \
    } while (0)

// store 8 k-consecutive tf32 values k-major: Sm[k..k+7][row] (PV A staging)
__device__ __forceinline__ void stg8(float (*Sm)[136], int kb, int row,
                                     float4 v0, float4 v1) {
    Sm[kb + 0][row] = __uint_as_float(cvt_tf32(v0.x));
    Sm[kb + 1][row] = __uint_as_float(cvt_tf32(v0.y));
    Sm[kb + 2][row] = __uint_as_float(cvt_tf32(v0.z));
    Sm[kb + 3][row] = __uint_as_float(cvt_tf32(v0.w));
    Sm[kb + 4][row] = __uint_as_float(cvt_tf32(v1.x));
    Sm[kb + 5][row] = __uint_as_float(cvt_tf32(v1.y));
    Sm[kb + 6][row] = __uint_as_float(cvt_tf32(v1.z));
    Sm[kb + 7][row] = __uint_as_float(cvt_tf32(v1.w));
}

struct GemmArgs {
    const float* A[3];
    const float* W[3];
    const float* bias[3];
    float*       C[3];
    float        alpha[3];
};

// ---------------------------------------------------------------------------
// NT GEMM + bias + alpha.  BM=BN=128, BK=16, 256 thr, 8 warps (2m x 4n),
// warp tile 64x32.  cp.async 2-stage staging, raw fp32 smem (pad 20).
// blockIdx.z selects the (A, W, bias, C, alpha) set.
// ---------------------------------------------------------------------------
__global__ __launch_bounds__(256) void gemm_nt_bias(
    GemmArgs ga, int K, int lda, int ldb, int ldc)
{
    const int z = blockIdx.z;
    const float* A    = ga.A[z];
    const float* Bm   = ga.W[z];
    const float* bias = ga.bias[z];
    float*       C    = ga.C[z];
    const float  alpha = ga.alpha[z];

    __shared__ float As[2][128][20];
    __shared__ float Bs[2][128][20];

    const int tid = threadIdx.x;
    const int lane = tid & 31, w = tid >> 5;
    const int wm = w & 1, wn = w >> 1;
    const int lr = lane >> 2, lc = lane & 3;
    const int bm = blockIdx.y * 128, bn = blockIdx.x * 128;
    const int row = tid >> 1, half = tid & 1;

    const float* Ag = A + (size_t)(bm + row) * lda + half * 8;
    const float* Bg = Bm + (size_t)(bn + row) * ldb + half * 8;
    const unsigned daBase = smem_u32(&As[0][row][half * 8]);
    const unsigned dbBase = smem_u32(&Bs[0][row][half * 8]);
    const unsigned bufStride = 128 * 20 * 4;

#define G_STAGE(kc, buf)                                                   \
    do {                                                                   \
        unsigned da = daBase + (buf) * bufStride;                          \
        unsigned db = dbBase + (buf) * bufStride;                          \
        CP16(da,      Ag + (kc) * 16);                                     \
        CP16(da + 16, Ag + (kc) * 16 + 4);                                 \
        CP16(db,      Bg + (kc) * 16);                                     \
        CP16(db + 16, Bg + (kc) * 16 + 4);                                 \
        CP_COMMIT();                                                       \
    } while (0)

    float acc[4][4][4] = {};

    const int NC = K >> 4;
    G_STAGE(0, 0);
    G_STAGE(1, 1);

    for (int kc = 0; kc < NC; kc++) {
        const int buf = kc & 1;
        if (kc + 1 < NC) CP_WAIT(1); else CP_WAIT(0);
        __syncthreads();
        K8_RAW(As[buf], Bs[buf], 0, wm * 64, wn * 32, acc);
        K8_RAW(As[buf], Bs[buf], 8, wm * 64, wn * 32, acc);
        __syncthreads();
        if (kc + 2 < NC) G_STAGE(kc + 2, buf);
    }
#undef G_STAGE

#pragma unroll
    for (int j = 0; j < 4; j++) {
        int col = bn + wn * 32 + j * 8 + lc * 2;
        float b0v = bias[col], b1v = bias[col + 1];
#pragma unroll
        for (int i = 0; i < 4; i++) {
            int r0 = bm + wm * 64 + i * 16 + lr;
            *(float2*)(C + (size_t)r0 * ldc + col) =
                make_float2(alpha * (acc[i][j][0] + b0v), alpha * (acc[i][j][1] + b1v));
            *(float2*)(C + (size_t)(r0 + 8) * ldc + col) =
                make_float2(alpha * (acc[i][j][2] + b0v), alpha * (acc[i][j][3] + b1v));
        }
    }
}

// ---------------------------------------------------------------------------
// Scores: per (b,h) 128x128 tile.  Computes clamp(Q.K^T) with mask, then
// writes e = exp(v - m_block) (block = this CTA's 128 cols) to P, and the
// per-(row, block) (m_block, s_block) to part.  Masked elements write 0.
// ---------------------------------------------------------------------------
__global__ __launch_bounds__(256) void attn_scores(
    const float* __restrict__ Qp, const float* __restrict__ Kp,
    const int* __restrict__ mask, float* __restrict__ P,
    float2* __restrict__ part)
{
    __shared__ float As[2][128][20];
    __shared__ float Bs[2][128][20];
    __shared__ float red_m[4][128];
    __shared__ float red_s[4][128];
    __shared__ int msk[128];

    const int bh = blockIdx.z, b = bh >> 4, h = bh & 15;
    float* C = P + (size_t)bh * T_ * S_;

    const int tid = threadIdx.x;
    const int lane = tid & 31, w = tid >> 5;
    const int wm = w & 1, wn = w >> 1;
    const int lr = lane >> 2, lc = lane & 3;
    const int bm = blockIdx.y * 128, bn = blockIdx.x * 128;
    const int row = tid >> 1, half = tid & 1;

    const float* Ag = Qp + (size_t)b * T_ * E_ + (size_t)(bm + row) * E_ + h * DH_ + half * 8;
    const float* Bg = Kp + (size_t)b * S_ * E_ + (size_t)(bn + row) * E_ + h * DH_ + half * 8;
    const unsigned daBase = smem_u32(&As[0][row][half * 8]);
    const unsigned dbBase = smem_u32(&Bs[0][row][half * 8]);
    const unsigned bufStride = 128 * 20 * 4;

#define S_STAGE(kc, buf)                                                   \
    do {                                                                   \
        unsigned da = daBase + (buf) * bufStride;                          \
        unsigned db = dbBase + (buf) * bufStride;                          \
        CP16(da,      Ag + (kc) * 16);                                     \
        CP16(da + 16, Ag + (kc) * 16 + 4);                                 \
        CP16(db,      Bg + (kc) * 16);                                     \
        CP16(db + 16, Bg + (kc) * 16 + 4);                                 \
        CP_COMMIT();                                                       \
    } while (0)

    if (tid < 128) msk[tid] = mask[(size_t)b * S_ + bn + tid];

    float acc[4][4][4] = {};

    S_STAGE(0, 0);
    S_STAGE(1, 1);

#pragma unroll
    for (int kc = 0; kc < 4; kc++) {
        const int buf = kc & 1;
        if (kc < 3) CP_WAIT(1); else CP_WAIT(0);
        __syncthreads();
        K8_RAW(As[buf], Bs[buf], 0, wm * 64, wn * 32, acc);
        K8_RAW(As[buf], Bs[buf], 8, wm * 64, wn * 32, acc);
        __syncthreads();
        if (kc < 2) S_STAGE(kc + 2, buf);
    }
#undef S_STAGE

    // helper: clamped + masked value
#define SCV(i, j, idx, keep) \
    ((keep) ? fminf(fmaxf(acc[i][j][idx], -CLAMP_V), CLAMP_V) : -INFINITY)

    // Phase 1: per-row max over this CTA's 128 cols (shfl across lc, smem across wn)
#pragma unroll
    for (int i = 0; i < 4; i++) {
        int rl = wm * 64 + i * 16 + lr;
        float m_lo = -INFINITY, m_hi = -INFINITY;
#pragma unroll
        for (int j = 0; j < 4; j++) {
            int lcol = wn * 32 + j * 8 + lc * 2;
            bool k0 = msk[lcol] != 0, k1 = msk[lcol + 1] != 0;
            m_lo = fmaxf(m_lo, fmaxf(SCV(i, j, 0, k0), SCV(i, j, 1, k1)));
            m_hi = fmaxf(m_hi, fmaxf(SCV(i, j, 2, k0), SCV(i, j, 3, k1)));
        }
#pragma unroll
        for (int off = 1; off <= 2; off <<= 1) {
            m_lo = fmaxf(m_lo, __shfl_xor_sync(0xffffffffu, m_lo, off));
            m_hi = fmaxf(m_hi, __shfl_xor_sync(0xffffffffu, m_hi, off));
        }
        if (lc == 0) {
            red_m[wn][rl]     = m_lo;
            red_m[wn][rl + 8] = m_hi;
        }
    }
    __syncthreads();

    // Phase 2: e = exp(v - m_block), store e, accumulate s
#pragma unroll
    for (int i = 0; i < 4; i++) {
        int rl = wm * 64 + i * 16 + lr;
        float mlo = fmaxf(fmaxf(red_m[0][rl], red_m[1][rl]),
                          fmaxf(red_m[2][rl], red_m[3][rl]));
        float mhi = fmaxf(fmaxf(red_m[0][rl + 8], red_m[1][rl + 8]),
                          fmaxf(red_m[2][rl + 8], red_m[3][rl + 8]));
        float mlou = (mlo == -INFINITY) ? 0.f : mlo;
        float mhiu = (mhi == -INFINITY) ? 0.f : mhi;
        float s_lo = 0.f, s_hi = 0.f;
#pragma unroll
        for (int j = 0; j < 4; j++) {
            int lcol = wn * 32 + j * 8 + lc * 2;
            bool k0 = msk[lcol] != 0, k1 = msk[lcol + 1] != 0;
            float e0 = __expf(SCV(i, j, 0, k0) - mlou);   // -inf -> 0
            float e1 = __expf(SCV(i, j, 1, k1) - mlou);
            float e2 = __expf(SCV(i, j, 2, k0) - mhiu);
            float e3 = __expf(SCV(i, j, 3, k1) - mhiu);
            s_lo += e0 + e1;
            s_hi += e2 + e3;
            int col = bn + lcol;
            *(float2*)(C + (size_t)(bm + rl) * S_ + col)     = make_float2(e0, e1);
            *(float2*)(C + (size_t)(bm + rl + 8) * S_ + col) = make_float2(e2, e3);
        }
#pragma unroll
        for (int off = 1; off <= 2; off <<= 1) {
            s_lo += __shfl_xor_sync(0xffffffffu, s_lo, off);
            s_hi += __shfl_xor_sync(0xffffffffu, s_hi, off);
        }
        if (lc == 0) {
            red_s[wn][rl]     = s_lo;
            red_s[wn][rl + 8] = s_hi;
        }
    }
    __syncthreads();

    if (tid < 128) {
        float m = fmaxf(fmaxf(red_m[0][tid], red_m[1][tid]),
                        fmaxf(red_m[2][tid], red_m[3][tid]));
        float s = red_s[0][tid] + red_s[1][tid] + red_s[2][tid] + red_s[3][tid];
        part[((size_t)bh * T_ + bm + tid) * NBLK + blockIdx.x] = make_float2(m, s);
    }
#undef SCV
}

// ---------------------------------------------------------------------------
// PV: builds per-(row, block) scale = exp(m_blk - m_glob)/s_glob from part,
// reads e from P, p = e * scale (NO exp in the loop), writes normalized p
// back, Ctx = P @ V.  BM=128, BN=64, BK=16, 256 thr, 8 warps (2m x 4n).
// ---------------------------------------------------------------------------
__global__ __launch_bounds__(256) void attn_pv(
    float* __restrict__ P, const float* __restrict__ Vp,
    const float2* __restrict__ part, float* __restrict__ Ctx)
{
    __shared__ float As[2][16][136];   // tf32, k-major
    __shared__ float Bs[2][16][72];    // raw fp32, k-major rows of V
    __shared__ float sh_scale[128][NBLK + 1];

    const int bh = blockIdx.y, b = bh >> 4, h = bh & 15;
    float* A = P + (size_t)bh * T_ * S_;
    const float* Vb = Vp + (size_t)b * S_ * E_ + h * DH_;
    float* C = Ctx + (size_t)b * T_ * E_ + h * DH_;

    const int tid = threadIdx.x;
    const int lane = tid & 31, w = tid >> 5;
    const int wm = w & 1, wn = w >> 1;
    const int lr = lane >> 2, lc = lane & 3;
    const int bm = blockIdx.x * 128;

    // per-row: merge block stats -> global (m, 1/s); scale per block
    if (tid < 128) {
        float pm[NBLK], ps[NBLK];
        float m = -INFINITY, s = 0.f;
#pragma unroll
        for (int j = 0; j < NBLK; j++) {
            float2 p = part[((size_t)bh * T_ + bm + tid) * NBLK + j];
            pm[j] = p.x; ps[j] = p.y;
            softmax_merge(m, s, p.x, p.y);
        }
        float inv = 1.f / s;
#pragma unroll
        for (int j = 0; j < NBLK; j++)
            sh_scale[tid][j] = (pm[j] == -INFINITY) ? 0.f : __expf(pm[j] - m) * inv;
    }
    __syncthreads();

    const int arow = tid >> 1, ak = (tid & 1) * 8;
    float* Pr = A + (size_t)(bm + arow) * S_ + ak;
    const float* scrow = sh_scale[arow];

    // B loader: 16 rows x 64 floats = 256 cp.16B, one per thread.
    const int vrow = tid >> 4, vseg = tid & 15;
    const unsigned dbBase = smem_u32(&Bs[0][vrow][vseg * 4]);
    const unsigned bufStrideB = 16 * 72 * 4;

#define PV_STAGE_B(kc, buf)                                                \
    do {                                                                   \
        CP16(dbBase + (buf) * bufStrideB,                                  \
             Vb + (size_t)((kc) * 16 + vrow) * E_ + vseg * 4);             \
        CP_COMMIT();                                                       \
    } while (0)

    float acc[4][2][4] = {};

    // prologue: A chunk 0 (scale+writeback+STS), B chunks 0,1 (async)
    {
        float sc = scrow[0];
        float4 a0 = *(float4*)(Pr);
        float4 a1 = *(float4*)(Pr + 4);
        a0.x *= sc; a0.y *= sc; a0.z *= sc; a0.w *= sc;
        a1.x *= sc; a1.y *= sc; a1.z *= sc; a1.w *= sc;
        *(float4*)(Pr)     = a0;
        *(float4*)(Pr + 4) = a1;
        stg8(As[0], ak, arow, a0, a1);
    }
    PV_STAGE_B(0, 0);
    PV_STAGE_B(1, 1);

    const int NC = S_ / 16;   // 128
    for (int kc = 0; kc < NC; kc++) {
        const int buf = kc & 1;
        const bool more = (kc + 1) < NC;
        float4 na0, na1;
        if (more) {
            float sc = scrow[(kc + 1) >> 3];
            na0 = *(float4*)(Pr + (kc + 1) * 16);
            na1 = *(float4*)(Pr + (kc + 1) * 16 + 4);
            na0.x *= sc; na0.y *= sc; na0.z *= sc; na0.w *= sc;
            na1.x *= sc; na1.y *= sc; na1.z *= sc; na1.w *= sc;
            *(float4*)(Pr + (kc + 1) * 16)     = na0;
            *(float4*)(Pr + (kc + 1) * 16 + 4) = na1;
        }
        if (kc + 1 < NC) CP_WAIT(1); else CP_WAIT(0);
        __syncthreads();
        // compute: A tf32 k-major, B raw k-major (cvt at load)
#pragma unroll
        for (int kt = 0; kt < 2; kt++) {
            const int kk = kt * 8;
            unsigned af[4][4], bf[2][2];
#pragma unroll
            for (int i = 0; i < 4; i++) {
                int mb = wm * 64 + i * 16 + lr;
                af[i][0] = __float_as_uint(As[buf][kk + lc][mb]);
                af[i][1] = __float_as_uint(As[buf][kk + lc][mb + 8]);
                af[i][2] = __float_as_uint(As[buf][kk + 4 + lc][mb]);
                af[i][3] = __float_as_uint(As[buf][kk + 4 + lc][mb + 8]);
            }
#pragma unroll
            for (int j = 0; j < 2; j++) {
                int nb = wn * 16 + j * 8 + lr;
                bf[j][0] = cvt_tf32(Bs[buf][kk + lc][nb]);
                bf[j][1] = cvt_tf32(Bs[buf][kk + 4 + lc][nb]);
            }
#pragma unroll
            for (int i = 0; i < 4; i++)
#pragma unroll
                for (int j = 0; j < 2; j++)
                    mma8(acc[i][j], af[i], bf[j]);
        }
        __syncthreads();
        if (more) {
            stg8(As[buf ^ 1], ak, arow, na0, na1);
            if (kc + 2 < NC) PV_STAGE_B(kc + 2, buf);
        }
    }
#undef PV_STAGE_B

#pragma unroll
    for (int j = 0; j < 2; j++) {
        int col = wn * 16 + j * 8 + lc * 2;
#pragma unroll
        for (int i = 0; i < 4; i++) {
            int r0 = bm + wm * 64 + i * 16 + lr;
            *(float2*)(C + (size_t)r0 * E_ + col)       = make_float2(acc[i][j][0], acc[i][j][1]);
            *(float2*)(C + (size_t)(r0 + 8) * E_ + col) = make_float2(acc[i][j][2], acc[i][j][3]);
        }
    }
}

// ---------------------------------------------------------------------------
extern "C" void kernel_launch(void* const* d_in, const int* in_sizes, int n_in,
                              void* d_out, int out_size)
{
    const float* q    = (const float*)d_in[0];
    const float* k    = (const float*)d_in[1];
    const float* v    = (const float*)d_in[2];
    const int*   mask = (const int*)d_in[3];
    const float* Wq   = (const float*)d_in[4];
    const float* bq   = (const float*)d_in[5];
    const float* Wk   = (const float*)d_in[6];
    const float* bk   = (const float*)d_in[7];
    const float* Wv   = (const float*)d_in[8];
    const float* bv   = (const float*)d_in[9];
    const float* Wo   = (const float*)d_in[10];
    const float* bo   = (const float*)d_in[11];

    float* out  = (float*)d_out;
    float* attn = out + (size_t)B_ * T_ * E_;

    float *Qp, *Kp, *Vp, *Ctx;
    float2 *part;
    cudaGetSymbolAddress((void**)&Qp, g_Qp);
    cudaGetSymbolAddress((void**)&Kp, g_Kp);
    cudaGetSymbolAddress((void**)&Vp, g_Vp);
    cudaGetSymbolAddress((void**)&Ctx, g_ctx);
    cudaGetSymbolAddress((void**)&part, g_part);

    dim3 gq(E_ / 128, (B_ * T_) / 128, 3);   // QKV fused: (8, 32, 3)
    GemmArgs g1;
    g1.A[0] = q;  g1.W[0] = Wq; g1.bias[0] = bq; g1.C[0] = Qp; g1.alpha[0] = SCALE_;
    g1.A[1] = k;  g1.W[1] = Wk; g1.bias[1] = bk; g1.C[1] = Kp; g1.alpha[1] = 1.0f;
    g1.A[2] = v;  g1.W[2] = Wv; g1.bias[2] = bv; g1.C[2] = Vp; g1.alpha[2] = 1.0f;
    gemm_nt_bias<<<gq, 256>>>(g1, E_, E_, E_, E_);

    attn_scores<<<dim3(S_ / 128, T_ / 128, B_ * H_), 256>>>(Qp, Kp, mask, attn, part);

    attn_pv<<<dim3(T_ / 128, B_ * H_), 256>>>(attn, Vp, part, Ctx);

    GemmArgs g2;
    g2.A[0] = Ctx; g2.W[0] = Wo; g2.bias[0] = bo; g2.C[0] = out; g2.alpha[0] = 1.0f;
    g2.A[1] = Ctx; g2.W[1] = Wo; g2.bias[1] = bo; g2.C[1] = out; g2.alpha[1] = 1.0f;
    g2.A[2] = Ctx; g2.W[2] = Wo; g2.bias[2] = bo; g2.C[2] = out; g2.alpha[2] = 1.0f;
    gemm_nt_bias<<<dim3(E_ / 128, (B_ * T_) / 128, 1), 256>>>(g2, E_, E_, E_, E_);
}

// round 10
// speedup vs baseline: 1.7047x; 1.0389x over previous
#include <cuda_runtime.h>
#include <math.h>

#define B_   2
#define T_   2048
#define S_   2048
#define E_   1024
#define H_   16
#define DH_  64
#define SCALE_ 0.125f
#define CLAMP_V 50000.0f
#define NBLK 16              // S_/128 stat blocks per row (pass 1)

// Scratch (device globals: no allocations allowed)
__device__ float  g_Qp[B_ * T_ * E_];
__device__ float  g_Kp[B_ * S_ * E_];
__device__ float  g_Vp[B_ * S_ * E_];
__device__ float  g_ctx[B_ * T_ * E_];
__device__ float2 g_part[(size_t)B_ * H_ * T_ * NBLK];

// ---------------------------------------------------------------------------
__device__ __forceinline__ unsigned smem_u32(const void* p) {
    unsigned r;
    asm("{ .reg .u64 t; cvta.to.shared.u64 t, %1; cvt.u32.u64 %0, t; }"
        : "=r"(r) : "l"(p));
    return r;
}

#define CP16(d, s) \
    asm volatile("cp.async.cg.shared.global [%0], [%1], 16;" :: "r"(d), "l"(s))
#define CP_COMMIT() asm volatile("cp.async.commit_group;" ::: "memory")
#define CP_WAIT(n)  asm volatile("cp.async.wait_group %0;" :: "n"(n) : "memory")

__device__ __forceinline__ unsigned cvt_tf32(float x) {
    unsigned r;
    asm("cvt.rna.tf32.f32 %0, %1;" : "=r"(r) : "f"(x));
    return r;
}
__device__ __forceinline__ float tf32f(float x) {
    return __uint_as_float(cvt_tf32(x));
}

__device__ __forceinline__ void mma8(float* d, const unsigned* a, const unsigned* b) {
    asm volatile(
        "mma.sync.aligned.m16n8k8.row.col.f32.tf32.tf32.f32 "
        "{%0,%1,%2,%3}, {%4,%5,%6,%7}, {%8,%9}, {%0,%1,%2,%3};"
        : "+f"(d[0]), "+f"(d[1]), "+f"(d[2]), "+f"(d[3])
        : "r"(a[0]), "r"(a[1]), "r"(a[2]), "r"(a[3]), "r"(b[0]), "r"(b[1]));
}

__device__ __forceinline__ void softmax_merge(float& m, float& s, float om, float os) {
    float nm = fmaxf(m, om);
    if (nm == -INFINITY) { m = nm; s = 0.f; return; }
    s = s * __expf(m - nm) + os * __expf(om - nm);
    m = nm;
}

// Fragment compute from RAW row-major smem (pad 20), cvt at load. 64x32 warp tile.
#define K8_RAW(As_, Bs_, kk, mbase, nbase, acc)                            \
    do {                                                                   \
        unsigned af[4][4], bf[4][2];                                       \
        _Pragma("unroll")                                                  \
        for (int i = 0; i < 4; i++) {                                      \
            int mr = (mbase) + i * 16 + lr;                                \
            af[i][0] = cvt_tf32((As_)[mr][(kk) + lc]);                     \
            af[i][1] = cvt_tf32((As_)[mr + 8][(kk) + lc]);                 \
            af[i][2] = cvt_tf32((As_)[mr][(kk) + 4 + lc]);                 \
            af[i][3] = cvt_tf32((As_)[mr + 8][(kk) + 4 + lc]);             \
        }                                                                  \
        _Pragma("unroll")                                                  \
        for (int j = 0; j < 4; j++) {                                      \
            int nr = (nbase) + j * 8 + lr;                                 \
            bf[j][0] = cvt_tf32((Bs_)[nr][(kk) + lc]);                     \
            bf[j][1] = cvt_tf32((Bs_)[nr][(kk) + 4 + lc]);                 \
        }                                                                  \
        _Pragma("unroll")                                                  \
        for (int i = 0; i < 4; i++)                                        \
            _Pragma("unroll")                                              \
            for (int j = 0; j < 4; j++)                                    \
                mma8(acc[i][j], af[i], bf[j]);                             \
    } while (0)

struct GemmArgs {
    const float* A[3];
    const float* W[3];
    const float* bias[3];
    float*       C[3];
    float        alpha[3];
};

// ---------------------------------------------------------------------------
// NT GEMM + bias + alpha (unchanged from R9): BM=BN=128, BK=16, 256 thr.
// ---------------------------------------------------------------------------
__global__ __launch_bounds__(256) void gemm_nt_bias(
    GemmArgs ga, int K, int lda, int ldb, int ldc)
{
    const int z = blockIdx.z;
    const float* A    = ga.A[z];
    const float* Bm   = ga.W[z];
    const float* bias = ga.bias[z];
    float*       C    = ga.C[z];
    const float  alpha = ga.alpha[z];

    __shared__ float As[2][128][20];
    __shared__ float Bs[2][128][20];

    const int tid = threadIdx.x;
    const int lane = tid & 31, w = tid >> 5;
    const int wm = w & 1, wn = w >> 1;
    const int lr = lane >> 2, lc = lane & 3;
    const int bm = blockIdx.y * 128, bn = blockIdx.x * 128;
    const int row = tid >> 1, half = tid & 1;

    const float* Ag = A + (size_t)(bm + row) * lda + half * 8;
    const float* Bg = Bm + (size_t)(bn + row) * ldb + half * 8;
    const unsigned daBase = smem_u32(&As[0][row][half * 8]);
    const unsigned dbBase = smem_u32(&Bs[0][row][half * 8]);
    const unsigned bufStride = 128 * 20 * 4;

#define G_STAGE(kc, buf)                                                   \
    do {                                                                   \
        unsigned da = daBase + (buf) * bufStride;                          \
        unsigned db = dbBase + (buf) * bufStride;                          \
        CP16(da,      Ag + (kc) * 16);                                     \
        CP16(da + 16, Ag + (kc) * 16 + 4);                                 \
        CP16(db,      Bg + (kc) * 16);                                     \
        CP16(db + 16, Bg + (kc) * 16 + 4);                                 \
        CP_COMMIT();                                                       \
    } while (0)

    float acc[4][4][4] = {};

    const int NC = K >> 4;
    G_STAGE(0, 0);
    G_STAGE(1, 1);

    for (int kc = 0; kc < NC; kc++) {
        const int buf = kc & 1;
        if (kc + 1 < NC) CP_WAIT(1); else CP_WAIT(0);
        __syncthreads();
        K8_RAW(As[buf], Bs[buf], 0, wm * 64, wn * 32, acc);
        K8_RAW(As[buf], Bs[buf], 8, wm * 64, wn * 32, acc);
        __syncthreads();
        if (kc + 2 < NC) G_STAGE(kc + 2, buf);
    }
#undef G_STAGE

#pragma unroll
    for (int j = 0; j < 4; j++) {
        int col = bn + wn * 32 + j * 8 + lc * 2;
        float b0v = bias[col], b1v = bias[col + 1];
#pragma unroll
        for (int i = 0; i < 4; i++) {
            int r0 = bm + wm * 64 + i * 16 + lr;
            *(float2*)(C + (size_t)r0 * ldc + col) =
                make_float2(alpha * (acc[i][j][0] + b0v), alpha * (acc[i][j][1] + b1v));
            *(float2*)(C + (size_t)(r0 + 8) * ldc + col) =
                make_float2(alpha * (acc[i][j][2] + b0v), alpha * (acc[i][j][3] + b1v));
        }
    }
}

// ---------------------------------------------------------------------------
// Pass 1 — stats only: per (b,h) 128x128 tile, computes clamp(Q.K^T)+mask,
// emits per-(row, block) (m, s) to part.  NO stores of the score matrix.
// ---------------------------------------------------------------------------
__global__ __launch_bounds__(256) void attn_stats(
    const float* __restrict__ Qp, const float* __restrict__ Kp,
    const int* __restrict__ mask, float2* __restrict__ part)
{
    __shared__ float As[2][128][20];
    __shared__ float Bs[2][128][20];
    __shared__ float red_m[4][128];
    __shared__ float red_s[4][128];
    __shared__ int msk[128];

    const int bh = blockIdx.z, b = bh >> 4, h = bh & 15;

    const int tid = threadIdx.x;
    const int lane = tid & 31, w = tid >> 5;
    const int wm = w & 1, wn = w >> 1;
    const int lr = lane >> 2, lc = lane & 3;
    const int bm = blockIdx.y * 128, bn = blockIdx.x * 128;
    const int row = tid >> 1, half = tid & 1;

    const float* Ag = Qp + (size_t)b * T_ * E_ + (size_t)(bm + row) * E_ + h * DH_ + half * 8;
    const float* Bg = Kp + (size_t)b * S_ * E_ + (size_t)(bn + row) * E_ + h * DH_ + half * 8;
    const unsigned daBase = smem_u32(&As[0][row][half * 8]);
    const unsigned dbBase = smem_u32(&Bs[0][row][half * 8]);
    const unsigned bufStride = 128 * 20 * 4;

#define S_STAGE(kc, buf)                                                   \
    do {                                                                   \
        unsigned da = daBase + (buf) * bufStride;                          \
        unsigned db = dbBase + (buf) * bufStride;                          \
        CP16(da,      Ag + (kc) * 16);                                     \
        CP16(da + 16, Ag + (kc) * 16 + 4);                                 \
        CP16(db,      Bg + (kc) * 16);                                     \
        CP16(db + 16, Bg + (kc) * 16 + 4);                                 \
        CP_COMMIT();                                                       \
    } while (0)

    if (tid < 128) msk[tid] = mask[(size_t)b * S_ + bn + tid];

    float acc[4][4][4] = {};

    S_STAGE(0, 0);
    S_STAGE(1, 1);

#pragma unroll
    for (int kc = 0; kc < 4; kc++) {
        const int buf = kc & 1;
        if (kc < 3) CP_WAIT(1); else CP_WAIT(0);
        __syncthreads();
        K8_RAW(As[buf], Bs[buf], 0, wm * 64, wn * 32, acc);
        K8_RAW(As[buf], Bs[buf], 8, wm * 64, wn * 32, acc);
        __syncthreads();
        if (kc < 2) S_STAGE(kc + 2, buf);
    }
#undef S_STAGE

#define SCV(i, j, idx, keep) \
    ((keep) ? fminf(fmaxf(acc[i][j][idx], -CLAMP_V), CLAMP_V) : -INFINITY)

    // Phase 1: per-row max across this CTA's 128 cols
#pragma unroll
    for (int i = 0; i < 4; i++) {
        int rl = wm * 64 + i * 16 + lr;
        float m_lo = -INFINITY, m_hi = -INFINITY;
#pragma unroll
        for (int j = 0; j < 4; j++) {
            int lcol = wn * 32 + j * 8 + lc * 2;
            bool k0 = msk[lcol] != 0, k1 = msk[lcol + 1] != 0;
            m_lo = fmaxf(m_lo, fmaxf(SCV(i, j, 0, k0), SCV(i, j, 1, k1)));
            m_hi = fmaxf(m_hi, fmaxf(SCV(i, j, 2, k0), SCV(i, j, 3, k1)));
        }
#pragma unroll
        for (int off = 1; off <= 2; off <<= 1) {
            m_lo = fmaxf(m_lo, __shfl_xor_sync(0xffffffffu, m_lo, off));
            m_hi = fmaxf(m_hi, __shfl_xor_sync(0xffffffffu, m_hi, off));
        }
        if (lc == 0) {
            red_m[wn][rl]     = m_lo;
            red_m[wn][rl + 8] = m_hi;
        }
    }
    __syncthreads();

    // Phase 2: s = sum exp(v - m_block)   (no stores)
#pragma unroll
    for (int i = 0; i < 4; i++) {
        int rl = wm * 64 + i * 16 + lr;
        float mlo = fmaxf(fmaxf(red_m[0][rl], red_m[1][rl]),
                          fmaxf(red_m[2][rl], red_m[3][rl]));
        float mhi = fmaxf(fmaxf(red_m[0][rl + 8], red_m[1][rl + 8]),
                          fmaxf(red_m[2][rl + 8], red_m[3][rl + 8]));
        float mlou = (mlo == -INFINITY) ? 0.f : mlo;
        float mhiu = (mhi == -INFINITY) ? 0.f : mhi;
        float s_lo = 0.f, s_hi = 0.f;
#pragma unroll
        for (int j = 0; j < 4; j++) {
            int lcol = wn * 32 + j * 8 + lc * 2;
            bool k0 = msk[lcol] != 0, k1 = msk[lcol + 1] != 0;
            s_lo += __expf(SCV(i, j, 0, k0) - mlou) + __expf(SCV(i, j, 1, k1) - mlou);
            s_hi += __expf(SCV(i, j, 2, k0) - mhiu) + __expf(SCV(i, j, 3, k1) - mhiu);
        }
#pragma unroll
        for (int off = 1; off <= 2; off <<= 1) {
            s_lo += __shfl_xor_sync(0xffffffffu, s_lo, off);
            s_hi += __shfl_xor_sync(0xffffffffu, s_hi, off);
        }
        if (lc == 0) {
            red_s[wn][rl]     = s_lo;
            red_s[wn][rl + 8] = s_hi;
        }
    }
    __syncthreads();

    if (tid < 128) {
        float m = fmaxf(fmaxf(red_m[0][tid], red_m[1][tid]),
                        fmaxf(red_m[2][tid], red_m[3][tid]));
        float s = red_s[0][tid] + red_s[1][tid] + red_s[2][tid] + red_s[3][tid];
        part[((size_t)bh * T_ + bm + tid) * NBLK + blockIdx.x] = make_float2(m, s);
    }
#undef SCV
}

// ---------------------------------------------------------------------------
// Pass 2 — fused: recompute QK^T per 64-col block (Q resident in smem),
// p = exp(clamp(v) - m_glob) * inv (mask -> 0), write p to attn ONCE,
// bounce p through tf32 smem tile, Ctx += P @ V in registers.
// Dynamic smem 101376 B; 2 CTAs/SM.
// Layout (floats): Q[128][68] | Ps[64][136] | Ks[2][64][20] | Vs[64][72] |
//                  st float2[128] | mk char[2048]
// ---------------------------------------------------------------------------
#define FZ_Q  0
#define FZ_P  8704
#define FZ_K  17408
#define FZ_V  19968
#define FZ_ST 24576
#define FZ_MK 24832
#define FZ_TOT 25344

__global__ __launch_bounds__(256, 2) void attn_fused(
    const float* __restrict__ Qp, const float* __restrict__ Kp,
    const float* __restrict__ Vp, const int* __restrict__ mask,
    const float2* __restrict__ part, float* __restrict__ P,
    float* __restrict__ Ctx)
{
    extern __shared__ float sm[];
    const int bh = blockIdx.y, b = bh >> 4, h = bh & 15;
    const int tid = threadIdx.x;
    const int lane = tid & 31, w = tid >> 5;
    const int wm = w & 1, wn = w >> 1;
    const int lr = lane >> 2, lc = lane & 3;
    const int bm = blockIdx.x * 128;
    const unsigned smb = smem_u32(sm);

    // row stats: merge 16 block partials -> (m_glob, 1/s)
    if (tid < 128) {
        float m = -INFINITY, s = 0.f;
#pragma unroll
        for (int j = 0; j < NBLK; j++) {
            float2 p = part[((size_t)bh * T_ + bm + tid) * NBLK + j];
            softmax_merge(m, s, p.x, p.y);
        }
        ((float2*)(sm + FZ_ST))[tid] = make_float2(m, 1.f / s);
    }
    // mask bytes for all S
    {
        char* mk = (char*)(sm + FZ_MK);
        const int* mg = mask + (size_t)b * S_;
#pragma unroll
        for (int u = 0; u < 8; u++) {
            int i = u * 256 + tid;
            mk[i] = (mg[i] != 0);
        }
    }
    // stage Q (rows bm..bm+127, 64 k) raw row-major [128][68]
    {
        const float* Qg = Qp + (size_t)b * T_ * E_ + (size_t)bm * E_ + h * DH_;
#pragma unroll
        for (int u = 0; u < 8; u++) {
            int lin = u * 256 + tid;
            int row = lin >> 4, seg = lin & 15;
            CP16(smb + (FZ_Q + row * 68 + seg * 4) * 4,
                 Qg + (size_t)row * E_ + seg * 4);
        }
        CP_COMMIT();
    }
    __syncthreads();   // stats + mask visible

    const float* Kg = Kp + (size_t)b * S_ * E_ + h * DH_;
    const float* Vg = Vp + (size_t)b * S_ * E_ + h * DH_;
    float* Pg = P + (size_t)bh * T_ * S_;
    const float2* st = (const float2*)(sm + FZ_ST);
    const char* mk = (const char*)(sm + FZ_MK);

    float acc_c[4][2][4] = {};

    for (int cb = 0; cb < 32; cb++) {
        float acc_s[4][2][4] = {};
        // stage V block (64 s-rows x 64 d) raw [64][72]
        {
#pragma unroll
            for (int u = 0; u < 4; u++) {
                int lin = u * 256 + tid;
                int row = lin >> 4, seg = lin & 15;
                CP16(smb + (FZ_V + row * 72 + seg * 4) * 4,
                     Vg + (size_t)(cb * 64 + row) * E_ + seg * 4);
            }
            CP_COMMIT();
        }
        // stage K chunks 0,1 (64 s-rows x 16 k each) raw [64][20]
        {
            int row = tid >> 2, seg = tid & 3;
            CP16(smb + (FZ_K + row * 20 + seg * 4) * 4,
                 Kg + (size_t)(cb * 64 + row) * E_ + seg * 4);
            CP_COMMIT();
            CP16(smb + (FZ_K + 1280 + row * 20 + seg * 4) * 4,
                 Kg + (size_t)(cb * 64 + row) * E_ + 16 + seg * 4);
            CP_COMMIT();
        }
        // scores: K = 64 in 4 chunks of 16
#pragma unroll
        for (int kc = 0; kc < 4; kc++) {
            if (kc < 3) CP_WAIT(1); else CP_WAIT(0);
            __syncthreads();
            const float* Qb = sm + FZ_Q;
            const float* Kb = sm + FZ_K + (kc & 1) * 1280;
#pragma unroll
            for (int kt = 0; kt < 2; kt++) {
                const int kk = kt * 8;
                unsigned af[4][4], bf[2][2];
#pragma unroll
                for (int i = 0; i < 4; i++) {
                    int mr = wm * 64 + i * 16 + lr;
                    af[i][0] = cvt_tf32(Qb[mr * 68 + kc * 16 + kk + lc]);
                    af[i][1] = cvt_tf32(Qb[(mr + 8) * 68 + kc * 16 + kk + lc]);
                    af[i][2] = cvt_tf32(Qb[mr * 68 + kc * 16 + kk + 4 + lc]);
                    af[i][3] = cvt_tf32(Qb[(mr + 8) * 68 + kc * 16 + kk + 4 + lc]);
                }
#pragma unroll
                for (int j = 0; j < 2; j++) {
                    int nb = wn * 16 + j * 8 + lr;
                    bf[j][0] = cvt_tf32(Kb[nb * 20 + kk + lc]);
                    bf[j][1] = cvt_tf32(Kb[nb * 20 + kk + 4 + lc]);
                }
#pragma unroll
                for (int i = 0; i < 4; i++)
#pragma unroll
                    for (int j = 0; j < 2; j++)
                        mma8(acc_s[i][j], af[i], bf[j]);
            }
            if (kc < 2) {
                __syncthreads();
                int row = tid >> 2, seg = tid & 3;
                CP16(smb + (FZ_K + (kc & 1) * 1280 + row * 20 + seg * 4) * 4,
                     Kg + (size_t)(cb * 64 + row) * E_ + (kc + 2) * 16 + seg * 4);
                CP_COMMIT();
            }
        }
        // epilogue: p = exp(clamp(v) - m)*inv (mask->0); write attn + Ps smem
        {
            float* Pb = sm + FZ_P;
#pragma unroll
            for (int i = 0; i < 4; i++) {
                int rl = wm * 64 + i * 16 + lr;
                float2 s0 = st[rl], s1 = st[rl + 8];
                float m0 = (s0.x == -INFINITY) ? 0.f : s0.x;
                float m1 = (s1.x == -INFINITY) ? 0.f : s1.x;
#pragma unroll
                for (int j = 0; j < 2; j++) {
                    int lcol = wn * 16 + j * 8 + lc * 2;
                    int gcol = cb * 64 + lcol;
                    bool k0 = mk[gcol] != 0, k1 = mk[gcol + 1] != 0;
                    float v00 = fminf(fmaxf(acc_s[i][j][0], -CLAMP_V), CLAMP_V);
                    float v01 = fminf(fmaxf(acc_s[i][j][1], -CLAMP_V), CLAMP_V);
                    float v10 = fminf(fmaxf(acc_s[i][j][2], -CLAMP_V), CLAMP_V);
                    float v11 = fminf(fmaxf(acc_s[i][j][3], -CLAMP_V), CLAMP_V);
                    float p00 = k0 ? __expf(v00 - m0) * s0.y : 0.f;
                    float p01 = k1 ? __expf(v01 - m0) * s0.y : 0.f;
                    float p10 = k0 ? __expf(v10 - m1) * s1.y : 0.f;
                    float p11 = k1 ? __expf(v11 - m1) * s1.y : 0.f;
                    *(float2*)(Pg + (size_t)(bm + rl) * S_ + gcol)     = make_float2(p00, p01);
                    *(float2*)(Pg + (size_t)(bm + rl + 8) * S_ + gcol) = make_float2(p10, p11);
                    Pb[lcol * 136 + rl]           = tf32f(p00);
                    Pb[(lcol + 1) * 136 + rl]     = tf32f(p01);
                    Pb[lcol * 136 + rl + 8]       = tf32f(p10);
                    Pb[(lcol + 1) * 136 + rl + 8] = tf32f(p11);
                }
            }
        }
        __syncthreads();
        // PV: Ctx += P(128x64) @ V(64x64), k = 64 from smem
        {
            const float* Pb = sm + FZ_P;
            const float* Vb = sm + FZ_V;
#pragma unroll
            for (int kt8 = 0; kt8 < 8; kt8++) {
                const int kk = kt8 * 8;
                unsigned af[4][4], bf[2][2];
#pragma unroll
                for (int i = 0; i < 4; i++) {
                    int mb = wm * 64 + i * 16 + lr;
                    af[i][0] = __float_as_uint(Pb[(kk + lc) * 136 + mb]);
                    af[i][1] = __float_as_uint(Pb[(kk + lc) * 136 + mb + 8]);
                    af[i][2] = __float_as_uint(Pb[(kk + 4 + lc) * 136 + mb]);
                    af[i][3] = __float_as_uint(Pb[(kk + 4 + lc) * 136 + mb + 8]);
                }
#pragma unroll
                for (int j = 0; j < 2; j++) {
                    int nb = wn * 16 + j * 8 + lr;
                    bf[j][0] = cvt_tf32(Vb[(kk + lc) * 72 + nb]);
                    bf[j][1] = cvt_tf32(Vb[(kk + 4 + lc) * 72 + nb]);
                }
#pragma unroll
                for (int i = 0; i < 4; i++)
#pragma unroll
                    for (int j = 0; j < 2; j++)
                        mma8(acc_c[i][j], af[i], bf[j]);
            }
        }
        __syncthreads();
    }

    // Ctx epilogue
    {
        float* Cg = Ctx + (size_t)b * T_ * E_ + h * DH_;
#pragma unroll
        for (int j = 0; j < 2; j++) {
            int col = wn * 16 + j * 8 + lc * 2;
#pragma unroll
            for (int i = 0; i < 4; i++) {
                int r0 = bm + wm * 64 + i * 16 + lr;
                *(float2*)(Cg + (size_t)r0 * E_ + col) =
                    make_float2(acc_c[i][j][0], acc_c[i][j][1]);
                *(float2*)(Cg + (size_t)(r0 + 8) * E_ + col) =
                    make_float2(acc_c[i][j][2], acc_c[i][j][3]);
            }
        }
    }
}

// ---------------------------------------------------------------------------
extern "C" void kernel_launch(void* const* d_in, const int* in_sizes, int n_in,
                              void* d_out, int out_size)
{
    const float* q    = (const float*)d_in[0];
    const float* k    = (const float*)d_in[1];
    const float* v    = (const float*)d_in[2];
    const int*   mask = (const int*)d_in[3];
    const float* Wq   = (const float*)d_in[4];
    const float* bq   = (const float*)d_in[5];
    const float* Wk   = (const float*)d_in[6];
    const float* bk   = (const float*)d_in[7];
    const float* Wv   = (const float*)d_in[8];
    const float* bv   = (const float*)d_in[9];
    const float* Wo   = (const float*)d_in[10];
    const float* bo   = (const float*)d_in[11];

    float* out  = (float*)d_out;
    float* attn = out + (size_t)B_ * T_ * E_;

    float *Qp, *Kp, *Vp, *Ctx;
    float2 *part;
    cudaGetSymbolAddress((void**)&Qp, g_Qp);
    cudaGetSymbolAddress((void**)&Kp, g_Kp);
    cudaGetSymbolAddress((void**)&Vp, g_Vp);
    cudaGetSymbolAddress((void**)&Ctx, g_ctx);
    cudaGetSymbolAddress((void**)&part, g_part);

    cudaFuncSetAttribute(attn_fused,
                         cudaFuncAttributeMaxDynamicSharedMemorySize,
                         FZ_TOT * 4);

    dim3 gq(E_ / 128, (B_ * T_) / 128, 3);   // QKV fused: (8, 32, 3)
    GemmArgs g1;
    g1.A[0] = q;  g1.W[0] = Wq; g1.bias[0] = bq; g1.C[0] = Qp; g1.alpha[0] = SCALE_;
    g1.A[1] = k;  g1.W[1] = Wk; g1.bias[1] = bk; g1.C[1] = Kp; g1.alpha[1] = 1.0f;
    g1.A[2] = v;  g1.W[2] = Wv; g1.bias[2] = bv; g1.C[2] = Vp; g1.alpha[2] = 1.0f;
    gemm_nt_bias<<<gq, 256>>>(g1, E_, E_, E_, E_);

    attn_stats<<<dim3(S_ / 128, T_ / 128, B_ * H_), 256>>>(Qp, Kp, mask, part);

    attn_fused<<<dim3(T_ / 128, B_ * H_), 256, FZ_TOT * 4>>>(
        Qp, Kp, Vp, mask, part, attn, Ctx);

    GemmArgs g2;
    g2.A[0] = Ctx; g2.W[0] = Wo; g2.bias[0] = bo; g2.C[0] = out; g2.alpha[0] = 1.0f;
    g2.A[1] = Ctx; g2.W[1] = Wo; g2.bias[1] = bo; g2.C[1] = out; g2.alpha[1] = 1.0f;
    g2.A[2] = Ctx; g2.W[2] = Wo; g2.bias[2] = bo; g2.C[2] = out; g2.alpha[2] = 1.0f;
    gemm_nt_bias<<<dim3(E_ / 128, (B_ * T_) / 128, 1), 256>>>(g2, E_, E_, E_, E_);
}